// round 1
// baseline (speedup 1.0000x reference)
#include <cuda_runtime.h>
#include <math.h>

// Problem constants (fixed by the dataset)
#define NN 50000
#define EE 640000
#define DD 128
#define RR 100
#define EPS 1e-5f

// ---------------- device scratch (no allocations allowed) ----------------
__device__ float g_x   [NN * DD];   // layer-1 input  (embedding gather)
__device__ float g_hl  [NN * DD];   // projected features (reused per layer)
__device__ float g_x2  [NN * DD];   // layer-2 input
__device__ float g_si  [NN];
__device__ float g_sj  [NN];
__device__ float g_rs  [RR];
__device__ int   g_off [NN + 1];    // CSR offsets by dst
__device__ int   g_cur [NN];        // fill cursors
__device__ int   g_es  [EE];        // src per edge, CSR order
__device__ int   g_et  [EE];        // edge type per edge, CSR order

// ---------------- CSR build ----------------
__global__ void zero_off_kernel() {
    int i = blockIdx.x * blockDim.x + threadIdx.x;
    if (i <= NN) g_off[i] = 0;
}

__global__ void count_kernel(const int* __restrict__ dst) {
    int e = blockIdx.x * blockDim.x + threadIdx.x;
    if (e < EE) atomicAdd(&g_off[dst[e]], 1);
}

// single-block exclusive scan over NN counts (in place), writes cursors too
__global__ void scan_kernel() {
    __shared__ int sh[1024];
    __shared__ int carry_s;
    int t = threadIdx.x;
    if (t == 0) carry_s = 0;
    __syncthreads();
    for (int base = 0; base < NN; base += 1024) {
        int i = base + t;
        int v = (i < NN) ? g_off[i] : 0;
        sh[t] = v;
        __syncthreads();
        #pragma unroll
        for (int o = 1; o < 1024; o <<= 1) {
            int tmp = (t >= o) ? sh[t - o] : 0;
            __syncthreads();
            sh[t] += tmp;
            __syncthreads();
        }
        int c = carry_s;
        int excl = c + sh[t] - v;
        if (i < NN) { g_off[i] = excl; g_cur[i] = excl; }
        __syncthreads();
        if (t == 1023) carry_s = c + sh[1023];
        __syncthreads();
    }
    if (t == 0) g_off[NN] = carry_s;
}

__global__ void fill_kernel(const int* __restrict__ src,
                            const int* __restrict__ dst,
                            const int* __restrict__ etype) {
    int e = blockIdx.x * blockDim.x + threadIdx.x;
    if (e >= EE) return;
    int d = dst[e];
    int pos = atomicAdd(&g_cur[d], 1);
    g_es[pos] = src[e];
    g_et[pos] = etype[e];
}

// ---------------- x = embedding[x_idx] ----------------
__global__ void gather_kernel(const int* __restrict__ x_idx,
                              const float* __restrict__ emb) {
    int tid = blockIdx.x * blockDim.x + threadIdx.x;  // N*32 float4s
    if (tid >= NN * 32) return;
    int row = tid >> 5, col = tid & 31;
    int s = x_idx[row];
    reinterpret_cast<float4*>(g_x)[tid] =
        reinterpret_cast<const float4*>(emb)[s * 32 + col];
}

// ---------------- per-relation score: rs[r] = rel_emb[r]·(Wr^T a_r) + br·a_r ----
__global__ void relscore_kernel(const float* __restrict__ rel_emb,
                                const float* __restrict__ Wr,
                                const float* __restrict__ br,
                                const float* __restrict__ attn) {
    __shared__ float v[DD];
    __shared__ float red[DD];
    const float* ar = attn + 2 * DD;
    int t = threadIdx.x;                     // 128 threads
    float acc = 0.f;
    #pragma unroll 4
    for (int d = 0; d < DD; d++) acc += Wr[d * DD + t] * ar[d];
    v[t] = acc;
    red[t] = br[t] * ar[t];
    __syncthreads();
    for (int s = 64; s > 0; s >>= 1) {
        if (t < s) red[t] += red[t + s];
        __syncthreads();
    }
    float c0 = red[0];
    int warp = t >> 5, lane = t & 31;
    for (int r = warp; r < RR; r += 4) {
        float p = 0.f;
        #pragma unroll
        for (int i = 0; i < 4; i++) {
            int k = lane + 32 * i;
            p += rel_emb[r * DD + k] * v[k];
        }
        #pragma unroll
        for (int o = 16; o; o >>= 1) p += __shfl_xor_sync(0xffffffffu, p, o);
        if (lane == 0) g_rs[r] = p + c0;
    }
}

// ---------------- GEMM: out[n,128] = X[n,128] @ W^T + b ----------------
// 256 threads/block, 64 rows/block. W transposed in smem, X tile in smem.
__global__ void gemm_kernel(const float* __restrict__ X,
                            const float* __restrict__ W,
                            const float* __restrict__ bias,
                            float* __restrict__ out) {
    extern __shared__ float sh[];
    float* Wt = sh;                 // [128][132]  Wt[k*132+j] = W[j][k]
    float* Xs = sh + 128 * 132;     // [64][128]
    int t = threadIdx.x;
    int blockRow = blockIdx.x * 64;

    for (int idx = t; idx < DD * DD; idx += 256) {
        int j = idx >> 7, k = idx & 127;
        Wt[k * 132 + j] = W[idx];                 // coalesced global read
    }
    const float4* X4 = reinterpret_cast<const float4*>(X);
    for (int idx = t; idx < 64 * 32; idx += 256) {
        int r = idx >> 5, c = idx & 31;
        int row = blockRow + r;
        float4 vv = (row < NN) ? X4[row * 32 + c] : make_float4(0.f, 0.f, 0.f, 0.f);
        reinterpret_cast<float4*>(Xs)[r * 32 + c] = vv;
    }
    __syncthreads();

    int colg = t & 31;   // cols colg*4 .. +3
    int rowg = t >> 5;   // rows rowg*8 .. +7
    float acc[8][4];
    #pragma unroll
    for (int r = 0; r < 8; r++)
        #pragma unroll
        for (int c = 0; c < 4; c++) acc[r][c] = 0.f;

    const float* Xbase = Xs + (rowg * 8) * DD;
    #pragma unroll 2
    for (int k = 0; k < DD; k++) {
        float4 w = *reinterpret_cast<const float4*>(&Wt[k * 132 + colg * 4]);
        #pragma unroll
        for (int r = 0; r < 8; r++) {
            float xv = Xbase[r * DD + k];          // warp-broadcast LDS
            acc[r][0] += xv * w.x;
            acc[r][1] += xv * w.y;
            acc[r][2] += xv * w.z;
            acc[r][3] += xv * w.w;
        }
    }
    float4 bv = *reinterpret_cast<const float4*>(&bias[colg * 4]);
    #pragma unroll
    for (int r = 0; r < 8; r++) {
        int row = blockRow + rowg * 8 + r;
        if (row < NN) {
            float4 o;
            o.x = acc[r][0] + bv.x;
            o.y = acc[r][1] + bv.y;
            o.z = acc[r][2] + bv.z;
            o.w = acc[r][3] + bv.w;
            *reinterpret_cast<float4*>(&out[row * DD + colg * 4]) = o;
        }
    }
}

// ---------------- per-node attention scores s_i = hl·a_i, s_j = hl·a_j ------
__global__ void scores_kernel(const float* __restrict__ hl,
                              const float* __restrict__ attn) {
    int w = (blockIdx.x * blockDim.x + threadIdx.x) >> 5;
    int lane = threadIdx.x & 31;
    if (w >= NN) return;
    float4 h  = reinterpret_cast<const float4*>(hl)[w * 32 + lane];
    float4 ai = reinterpret_cast<const float4*>(attn)[lane];
    float4 aj = reinterpret_cast<const float4*>(attn)[32 + lane];
    float pi = h.x * ai.x + h.y * ai.y + h.z * ai.z + h.w * ai.w;
    float pj = h.x * aj.x + h.y * aj.y + h.z * aj.z + h.w * aj.w;
    #pragma unroll
    for (int o = 16; o; o >>= 1) {
        pi += __shfl_xor_sync(0xffffffffu, pi, o);
        pj += __shfl_xor_sync(0xffffffffu, pj, o);
    }
    if (lane == 0) { g_si[w] = pi; g_sj[w] = pj; }
}

// ---------------- warp-per-dst online-softmax aggregate + residual + LN + ReLU
__global__ void aggregate_kernel(const float* __restrict__ xin,
                                 const float* __restrict__ hl,
                                 const float* __restrict__ gamma,
                                 const float* __restrict__ beta,
                                 float* __restrict__ xout) {
    int w = (blockIdx.x * blockDim.x + threadIdx.x) >> 5;
    int lane = threadIdx.x & 31;
    if (w >= NN) return;

    int beg = g_off[w], end = g_off[w + 1];
    float si = g_si[w];
    float m = -3.402823466e38f, den = 0.f;
    float ax = 0.f, ay = 0.f, az = 0.f, aw = 0.f;

    for (int e = beg; e < end; e++) {
        int s  = g_es[e];
        int ty = g_et[e];
        float al = si + g_sj[s] + g_rs[ty];
        al = (al > 0.f) ? al : 0.2f * al;         // leaky_relu(., 0.2)
        float mn = fmaxf(m, al);
        float sc = __expf(m - mn);                 // 0 on first edge
        float p  = __expf(al - mn);
        float4 h = *reinterpret_cast<const float4*>(&hl[s * DD + lane * 4]);
        ax = ax * sc + p * h.x;
        ay = ay * sc + p * h.y;
        az = az * sc + p * h.z;
        aw = aw * sc + p * h.w;
        den = den * sc + p;
        m = mn;
    }
    float inv = (den > 0.f) ? (1.f / den) : 0.f;

    float4 xi = *reinterpret_cast<const float4*>(&xin[w * DD + lane * 4]);
    float yx = xi.x + ax * inv;
    float yy = xi.y + ay * inv;
    float yz = xi.z + az * inv;
    float yw = xi.w + aw * inv;

    // LayerNorm across the 128-wide row held by this warp
    float sum = yx + yy + yz + yw;
    #pragma unroll
    for (int o = 16; o; o >>= 1) sum += __shfl_xor_sync(0xffffffffu, sum, o);
    float mu = sum * (1.f / 128.f);
    float dx = yx - mu, dy = yy - mu, dz = yz - mu, dw = yw - mu;
    float sq = dx * dx + dy * dy + dz * dz + dw * dw;
    #pragma unroll
    for (int o = 16; o; o >>= 1) sq += __shfl_xor_sync(0xffffffffu, sq, o);
    float var = sq * (1.f / 128.f);
    float rs = rsqrtf(var + EPS);

    float4 g4 = *reinterpret_cast<const float4*>(&gamma[lane * 4]);
    float4 b4 = *reinterpret_cast<const float4*>(&beta[lane * 4]);
    float4 o;
    o.x = fmaxf(0.f, dx * rs * g4.x + b4.x);
    o.y = fmaxf(0.f, dy * rs * g4.y + b4.y);
    o.z = fmaxf(0.f, dz * rs * g4.z + b4.z);
    o.w = fmaxf(0.f, dw * rs * g4.w + b4.w);
    *reinterpret_cast<float4*>(&xout[w * DD + lane * 4]) = o;
}

// ---------------- launch ----------------
extern "C" void kernel_launch(void* const* d_in, const int* in_sizes, int n_in,
                              void* d_out, int out_size) {
    const int*   x_idx   = (const int*)  d_in[0];
    const int*   eidx    = (const int*)  d_in[1];   // (2,E): [src..., dst...]
    const int*   etype   = (const int*)  d_in[2];
    const float* emb     = (const float*)d_in[3];
    const float* rel_emb = (const float*)d_in[4];
    const float* W1      = (const float*)d_in[5];
    const float* b1      = (const float*)d_in[6];
    const float* Wr1     = (const float*)d_in[7];
    const float* br1     = (const float*)d_in[8];
    const float* attn1   = (const float*)d_in[9];
    const float* g1      = (const float*)d_in[10];
    const float* be1     = (const float*)d_in[11];
    const float* W2      = (const float*)d_in[12];
    const float* b2      = (const float*)d_in[13];
    const float* Wr2     = (const float*)d_in[14];
    const float* br2     = (const float*)d_in[15];
    const float* attn2   = (const float*)d_in[16];
    const float* g2      = (const float*)d_in[17];
    const float* be2     = (const float*)d_in[18];
    float* out = (float*)d_out;

    const int* src = eidx;
    const int* dst = eidx + EE;

    // raw device pointers to globals (host must use the runtime for launches only;
    // kernels reference the globals directly)
    float* px  = nullptr; cudaGetSymbolAddress((void**)&px,  g_x);
    float* phl = nullptr; cudaGetSymbolAddress((void**)&phl, g_hl);
    float* px2 = nullptr; cudaGetSymbolAddress((void**)&px2, g_x2);

    const int gemm_smem = (128 * 132 + 64 * 128) * (int)sizeof(float);   // 100352
    cudaFuncSetAttribute(gemm_kernel, cudaFuncAttributeMaxDynamicSharedMemorySize,
                         gemm_smem);

    // ---- CSR build (shared by both layers) ----
    zero_off_kernel<<<(NN + 256) / 256, 256>>>();
    count_kernel<<<(EE + 255) / 256, 256>>>(dst);
    scan_kernel<<<1, 1024>>>();
    fill_kernel<<<(EE + 255) / 256, 256>>>(src, dst, etype);

    // ---- x = embedding[x_idx] ----
    gather_kernel<<<(NN * 32 + 255) / 256, 256>>>(x_idx, emb);

    const int gemm_blocks = (NN + 63) / 64;
    const int warp_blocks = (NN * 32 + 255) / 256;

    // ---- layer 1 ----
    relscore_kernel<<<1, 128>>>(rel_emb, Wr1, br1, attn1);
    gemm_kernel<<<gemm_blocks, 256, gemm_smem>>>(px, W1, b1, phl);
    scores_kernel<<<warp_blocks, 256>>>(phl, attn1);
    aggregate_kernel<<<warp_blocks, 256>>>(px, phl, g1, be1, px2);

    // ---- layer 2 ----
    relscore_kernel<<<1, 128>>>(rel_emb, Wr2, br2, attn2);
    gemm_kernel<<<gemm_blocks, 256, gemm_smem>>>(px2, W2, b2, phl);
    scores_kernel<<<warp_blocks, 256>>>(phl, attn2);
    aggregate_kernel<<<warp_blocks, 256>>>(px2, phl, g2, be2, out);
}

// round 3
// speedup vs baseline: 1.2047x; 1.2047x over previous
#include <cuda_runtime.h>
#include <cstdint>
#include <math.h>

#define NN 50000
#define EE 640000
#define DD 128
#define RR 100
#define EPS 1e-5f

// ---------------- device scratch ----------------
__device__ float    g_hl  [NN * DD];
__device__ float    g_x2  [NN * DD];
__device__ float    g_si  [NN];
__device__ float    g_sj  [NN];
__device__ float    g_rs  [RR];
__device__ int      g_off [NN + 1];
__device__ int      g_cur [NN];
__device__ int      g_scan[NN];
__device__ int      g_bsum[64];
__device__ unsigned g_ep  [EE];      // src | (etype<<17), CSR order

__device__ __forceinline__ uint32_t f2tf32(float x) {
    uint32_t r;
    asm("cvt.rna.tf32.f32 %0, %1;" : "=r"(r) : "f"(x));
    return r;
}

// m16n8k8 row.col tf32 MMA, D += A*B
__device__ __forceinline__ void mma_tf32(float* d, const uint32_t* a, const uint32_t* b) {
    asm volatile(
        "mma.sync.aligned.m16n8k8.row.col.f32.tf32.tf32.f32 "
        "{%0,%1,%2,%3}, {%4,%5,%6,%7}, {%8,%9}, {%0,%1,%2,%3};"
        : "+f"(d[0]), "+f"(d[1]), "+f"(d[2]), "+f"(d[3])
        : "r"(a[0]), "r"(a[1]), "r"(a[2]), "r"(a[3]), "r"(b[0]), "r"(b[1]));
}

// ================= CSR build =================
__global__ void zero_off_kernel() {
    int i = blockIdx.x * blockDim.x + threadIdx.x;
    if (i <= NN) g_off[i] = 0;
}
__global__ void count_kernel(const int* __restrict__ dst) {
    int e = blockIdx.x * blockDim.x + threadIdx.x;
    if (e < EE) atomicAdd(&g_off[dst[e]], 1);
}
__global__ void scan1_kernel() {   // per-block inclusive scan
    __shared__ int sh[1024];
    int t = threadIdx.x;
    int i = blockIdx.x * 1024 + t;
    int v = (i < NN) ? g_off[i] : 0;
    sh[t] = v;
    __syncthreads();
    #pragma unroll
    for (int o = 1; o < 1024; o <<= 1) {
        int x = (t >= o) ? sh[t - o] : 0;
        __syncthreads();
        sh[t] += x;
        __syncthreads();
    }
    if (i < NN) g_scan[i] = sh[t];
    if (t == 1023) g_bsum[blockIdx.x] = sh[1023];
}
__global__ void scan2_kernel() {   // scan 49 block sums -> exclusive
    __shared__ int sh[64];
    int t = threadIdx.x;   // 64 threads
    int v = (t < 49) ? g_bsum[t] : 0;
    sh[t] = v;
    __syncthreads();
    #pragma unroll
    for (int o = 1; o < 64; o <<= 1) {
        int x = (t >= o) ? sh[t - o] : 0;
        __syncthreads();
        sh[t] += x;
        __syncthreads();
    }
    if (t < 49) g_bsum[t] = sh[t] - v;
    if (t == 48) g_off[NN] = sh[48];
}
__global__ void scan3_kernel() {
    int i = blockIdx.x * blockDim.x + threadIdx.x;
    if (i >= NN) return;
    int cnt = g_off[i];
    int excl = g_bsum[i >> 10] + g_scan[i] - cnt;
    g_off[i] = excl;
    g_cur[i] = excl;
}
__global__ void fill_kernel(const int* __restrict__ src,
                            const int* __restrict__ dst,
                            const int* __restrict__ etype) {
    int e = blockIdx.x * blockDim.x + threadIdx.x;
    if (e >= EE) return;
    int d = dst[e];
    int pos = atomicAdd(&g_cur[d], 1);
    g_ep[pos] = (unsigned)src[e] | ((unsigned)etype[e] << 17);
}

// ====== per-relation score: rs[r] = rel_emb[r]·(Wr^T a_r) + br·a_r ==========
__global__ void relscore_kernel(const float* __restrict__ rel_emb,
                                const float* __restrict__ Wr,
                                const float* __restrict__ br,
                                const float* __restrict__ attn) {
    __shared__ float v[DD];
    __shared__ float red[DD];
    const float* ar = attn + 2 * DD;
    int t = threadIdx.x;  // 128
    float acc = 0.f;
    #pragma unroll 4
    for (int d = 0; d < DD; d++) acc += Wr[d * DD + t] * ar[d];
    v[t] = acc;
    red[t] = br[t] * ar[t];
    __syncthreads();
    for (int s = 64; s > 0; s >>= 1) {
        if (t < s) red[t] += red[t + s];
        __syncthreads();
    }
    float c0 = red[0];
    int warp = t >> 5, lane = t & 31;
    for (int r = warp; r < RR; r += 4) {
        float p = 0.f;
        #pragma unroll
        for (int i = 0; i < 4; i++) p += rel_emb[r * DD + lane + 32 * i] * v[lane + 32 * i];
        #pragma unroll
        for (int o = 16; o; o >>= 1) p += __shfl_xor_sync(0xffffffffu, p, o);
        if (lane == 0) g_rs[r] = p + c0;
    }
}

// ====== tensor-core GEMM (mma.sync tf32, 3-term split) + bias + scores ======
// hl[row] = X[idx?idx[row]:row] @ W^T + b ; also s_i = hl·a_i, s_j = hl·a_j.
// 256 threads, 128 rows/block. smem: X fp32 [128][132], Whi/Wlo tf32 [k=128][n=132].
#define LDPAD 132
__global__ __launch_bounds__(256, 1) void gemm_mma_kernel(
    const float* __restrict__ X, const int* __restrict__ idx,
    const float* __restrict__ W, const float* __restrict__ bias,
    const float* __restrict__ attn, float* __restrict__ hl) {
    extern __shared__ float sh[];
    float*    Xs  = sh;                       // 128*132 floats
    uint32_t* Whi = (uint32_t*)(sh + 128 * LDPAD);
    uint32_t* Wlo = Whi + 128 * LDPAD;

    int tid = threadIdx.x;
    int blockRow = blockIdx.x * 128;

    // W[j][k] (row-major) -> smem[k][j], split hi/lo tf32
    for (int i = tid; i < DD * DD; i += 256) {
        int j = i >> 7, k = i & 127;
        float w = W[i];
        uint32_t h = f2tf32(w);
        Whi[k * LDPAD + j] = h;
        Wlo[k * LDPAD + j] = f2tf32(w - __uint_as_float(h));
    }
    // X tile (gathered)
    for (int i = tid; i < 128 * 32; i += 256) {
        int r = i >> 5, c = i & 31;
        int row = blockRow + r;
        float4 v = make_float4(0.f, 0.f, 0.f, 0.f);
        if (row < NN) {
            int g = idx ? idx[row] : row;
            v = ((const float4*)X)[(size_t)g * 32 + c];
        }
        *(float4*)&Xs[r * LDPAD + c * 4] = v;
    }
    __syncthreads();

    int wid = tid >> 5, lane = tid & 31;
    int gid = lane >> 2, tig = lane & 3;

    float acc[16][4];
    #pragma unroll
    for (int nt = 0; nt < 16; nt++)
        #pragma unroll
        for (int q = 0; q < 4; q++) acc[nt][q] = 0.f;

    const float* xa = &Xs[(wid * 16 + gid) * LDPAD];

    for (int k0 = 0; k0 < 16; k0++) {
        int kb = k0 * 8;
        float a0f = xa[kb + tig];
        float a1f = xa[8 * LDPAD + kb + tig];
        float a2f = xa[kb + tig + 4];
        float a3f = xa[8 * LDPAD + kb + tig + 4];
        uint32_t ahi[4], alo[4];
        ahi[0] = f2tf32(a0f); alo[0] = f2tf32(a0f - __uint_as_float(ahi[0]));
        ahi[1] = f2tf32(a1f); alo[1] = f2tf32(a1f - __uint_as_float(ahi[1]));
        ahi[2] = f2tf32(a2f); alo[2] = f2tf32(a2f - __uint_as_float(ahi[2]));
        ahi[3] = f2tf32(a3f); alo[3] = f2tf32(a3f - __uint_as_float(ahi[3]));

        const uint32_t* bh0 = Whi + (kb + tig) * LDPAD + gid;
        const uint32_t* bh1 = Whi + (kb + tig + 4) * LDPAD + gid;
        const uint32_t* bl0 = Wlo + (kb + tig) * LDPAD + gid;
        const uint32_t* bl1 = Wlo + (kb + tig + 4) * LDPAD + gid;

        #pragma unroll
        for (int nt = 0; nt < 16; nt++) {
            uint32_t bh[2] = { bh0[nt * 8], bh1[nt * 8] };
            uint32_t bl[2] = { bl0[nt * 8], bl1[nt * 8] };
            mma_tf32(acc[nt], ahi, bh);
            mma_tf32(acc[nt], alo, bh);
            mma_tf32(acc[nt], ahi, bl);
        }
    }

    // epilogue: bias, store hl, fused attention scores
    int r0 = blockRow + wid * 16 + gid;
    int r1 = r0 + 8;
    float si0 = 0.f, sj0 = 0.f, si1 = 0.f, sj1 = 0.f;
    #pragma unroll
    for (int nt = 0; nt < 16; nt++) {
        int c0 = nt * 8 + tig * 2;
        float bb0 = bias[c0], bb1 = bias[c0 + 1];
        float v00 = acc[nt][0] + bb0, v01 = acc[nt][1] + bb1;
        float v10 = acc[nt][2] + bb0, v11 = acc[nt][3] + bb1;
        float ai0 = attn[c0], ai1 = attn[c0 + 1];
        float aj0 = attn[DD + c0], aj1 = attn[DD + c0 + 1];
        si0 += v00 * ai0 + v01 * ai1;
        sj0 += v00 * aj0 + v01 * aj1;
        si1 += v10 * ai0 + v11 * ai1;
        sj1 += v10 * aj0 + v11 * aj1;
        if (r0 < NN) *(float2*)&hl[(size_t)r0 * DD + c0] = make_float2(v00, v01);
        if (r1 < NN) *(float2*)&hl[(size_t)r1 * DD + c0] = make_float2(v10, v11);
    }
    #pragma unroll
    for (int o = 1; o <= 2; o <<= 1) {
        si0 += __shfl_xor_sync(0xffffffffu, si0, o);
        sj0 += __shfl_xor_sync(0xffffffffu, sj0, o);
        si1 += __shfl_xor_sync(0xffffffffu, si1, o);
        sj1 += __shfl_xor_sync(0xffffffffu, sj1, o);
    }
    if (tig == 0) {
        if (r0 < NN) { g_si[r0] = si0; g_sj[r0] = sj0; }
        if (r1 < NN) { g_si[r1] = si1; g_sj[r1] = sj1; }
    }
}

// ====== warp-per-dst online-softmax aggregate + residual + LN + ReLU =========
__global__ void aggregate_kernel(const float* __restrict__ xin,
                                 const int* __restrict__ idx,
                                 const float* __restrict__ hl,
                                 const float* __restrict__ gamma,
                                 const float* __restrict__ beta,
                                 float* __restrict__ xout) {
    int w = (blockIdx.x * blockDim.x + threadIdx.x) >> 5;
    int lane = threadIdx.x & 31;
    if (w >= NN) return;

    int beg = g_off[w], end = g_off[w + 1];
    float si = g_si[w];
    float m = -3.402823466e38f, den = 0.f;
    float ax = 0.f, ay = 0.f, az = 0.f, aw = 0.f;

    for (int e = beg; e < end; e++) {
        unsigned p = g_ep[e];
        int s = (int)(p & 0x1FFFFu);
        int ty = (int)(p >> 17);
        float al = si + g_sj[s] + g_rs[ty];
        al = (al > 0.f) ? al : 0.2f * al;
        float mn = fmaxf(m, al);
        float sc = __expf(m - mn);
        float pe = __expf(al - mn);
        float4 h = *(const float4*)&hl[(size_t)s * DD + lane * 4];
        ax = ax * sc + pe * h.x;
        ay = ay * sc + pe * h.y;
        az = az * sc + pe * h.z;
        aw = aw * sc + pe * h.w;
        den = den * sc + pe;
        m = mn;
    }
    float inv = (den > 0.f) ? (1.f / den) : 0.f;

    int xrow = idx ? idx[w] : w;
    float4 xi = *(const float4*)&xin[(size_t)xrow * DD + lane * 4];
    float yx = xi.x + ax * inv;
    float yy = xi.y + ay * inv;
    float yz = xi.z + az * inv;
    float yw = xi.w + aw * inv;

    float sum = yx + yy + yz + yw;
    #pragma unroll
    for (int o = 16; o; o >>= 1) sum += __shfl_xor_sync(0xffffffffu, sum, o);
    float mu = sum * (1.f / 128.f);
    float dx = yx - mu, dy = yy - mu, dz = yz - mu, dw = yw - mu;
    float sq = dx * dx + dy * dy + dz * dz + dw * dw;
    #pragma unroll
    for (int o = 16; o; o >>= 1) sq += __shfl_xor_sync(0xffffffffu, sq, o);
    float var = sq * (1.f / 128.f);
    float rsd = rsqrtf(var + EPS);

    float4 g4 = *(const float4*)&gamma[lane * 4];
    float4 b4 = *(const float4*)&beta[lane * 4];
    float4 o;
    o.x = fmaxf(0.f, dx * rsd * g4.x + b4.x);
    o.y = fmaxf(0.f, dy * rsd * g4.y + b4.y);
    o.z = fmaxf(0.f, dz * rsd * g4.z + b4.z);
    o.w = fmaxf(0.f, dw * rsd * g4.w + b4.w);
    *(float4*)&xout[(size_t)w * DD + lane * 4] = o;
}

// ---------------- launch ----------------
extern "C" void kernel_launch(void* const* d_in, const int* in_sizes, int n_in,
                              void* d_out, int out_size) {
    const int*   x_idx   = (const int*)  d_in[0];
    const int*   eidx    = (const int*)  d_in[1];
    const int*   etype   = (const int*)  d_in[2];
    const float* emb     = (const float*)d_in[3];
    const float* rel_emb = (const float*)d_in[4];
    const float* W1      = (const float*)d_in[5];
    const float* b1      = (const float*)d_in[6];
    const float* Wr1     = (const float*)d_in[7];
    const float* br1     = (const float*)d_in[8];
    const float* attn1   = (const float*)d_in[9];
    const float* g1      = (const float*)d_in[10];
    const float* be1     = (const float*)d_in[11];
    const float* W2      = (const float*)d_in[12];
    const float* b2      = (const float*)d_in[13];
    const float* Wr2     = (const float*)d_in[14];
    const float* br2     = (const float*)d_in[15];
    const float* attn2   = (const float*)d_in[16];
    const float* g2      = (const float*)d_in[17];
    const float* be2     = (const float*)d_in[18];
    float* out = (float*)d_out;

    const int* src = eidx;
    const int* dst = eidx + EE;

    float* phl = nullptr; cudaGetSymbolAddress((void**)&phl, g_hl);
    float* px2 = nullptr; cudaGetSymbolAddress((void**)&px2, g_x2);

    const int gemm_smem = 3 * 128 * LDPAD * (int)sizeof(float);   // 202752
    cudaFuncSetAttribute(gemm_mma_kernel,
                         cudaFuncAttributeMaxDynamicSharedMemorySize, gemm_smem);

    const int gemm_blocks = (NN + 127) / 128;          // 391
    const int warp_blocks = (NN * 32 + 255) / 256;

    zero_off_kernel<<<(NN + 256) / 256, 256>>>();
    count_kernel<<<(EE + 255) / 256, 256>>>(dst);
    scan1_kernel<<<(NN + 1023) / 1024, 1024>>>();
    scan2_kernel<<<1, 64>>>();
    scan3_kernel<<<(NN + 255) / 256, 256>>>();

    // layer 1 GEMM (independent of CSR)
    gemm_mma_kernel<<<gemm_blocks, 256, gemm_smem>>>(emb, x_idx, W1, b1, attn1, phl);

    fill_kernel<<<(EE + 255) / 256, 256>>>(src, dst, etype);
    relscore_kernel<<<1, 128>>>(rel_emb, Wr1, br1, attn1);
    aggregate_kernel<<<warp_blocks, 256>>>(emb, x_idx, phl, g1, be1, px2);

    // layer 2
    relscore_kernel<<<1, 128>>>(rel_emb, Wr2, br2, attn2);
    gemm_mma_kernel<<<gemm_blocks, 256, gemm_smem>>>(px2, nullptr, W2, b2, attn2, phl);
    aggregate_kernel<<<warp_blocks, 256>>>(px2, nullptr, phl, g2, be2, out);
}

// round 4
// speedup vs baseline: 1.2147x; 1.0084x over previous
#include <cuda_runtime.h>
#include <cstdint>
#include <math.h>

#define NN 50000
#define EE 640000
#define DD 128
#define RR 100
#define EPS 1e-5f

// ---------------- device scratch ----------------
__device__ float    g_hl   [NN * DD];
__device__ float    g_x2   [NN * DD];
__device__ float    g_si   [NN];
__device__ float    g_sj   [NN];
__device__ float    g_rs   [RR];
__device__ int      g_off  [NN + 1];
__device__ int      g_cur  [NN];
__device__ int      g_scan [NN];
__device__ int      g_bsum [64];
__device__ uint2    g_e2   [EE];     // {src | (etype<<17), dst}, CSR order
__device__ float    g_alpha[EE];     // leaky-relu'd attention logit per edge

__device__ __forceinline__ uint32_t f2tf32(float x) {
    uint32_t r;
    asm("cvt.rna.tf32.f32 %0, %1;" : "=r"(r) : "f"(x));
    return r;
}

// m16n8k8 row.col tf32 MMA, D += A*B
__device__ __forceinline__ void mma_tf32(float* d, const uint32_t* a, const uint32_t* b) {
    asm volatile(
        "mma.sync.aligned.m16n8k8.row.col.f32.tf32.tf32.f32 "
        "{%0,%1,%2,%3}, {%4,%5,%6,%7}, {%8,%9}, {%0,%1,%2,%3};"
        : "+f"(d[0]), "+f"(d[1]), "+f"(d[2]), "+f"(d[3])
        : "r"(a[0]), "r"(a[1]), "r"(a[2]), "r"(a[3]), "r"(b[0]), "r"(b[1]));
}

// ================= CSR build =================
__global__ void zero_off_kernel() {
    int i = blockIdx.x * blockDim.x + threadIdx.x;
    if (i <= NN) g_off[i] = 0;
}
__global__ void count_kernel(const int* __restrict__ dst) {
    int e = blockIdx.x * blockDim.x + threadIdx.x;
    if (e < EE) atomicAdd(&g_off[dst[e]], 1);
}
// per-block (1024) inclusive scan via warp shuffles
__global__ void scan1_kernel() {
    __shared__ int wsum[32];
    int t = threadIdx.x, lane = t & 31, w = t >> 5;
    int i = blockIdx.x * 1024 + t;
    int v = (i < NN) ? g_off[i] : 0;
    int x = v;
    #pragma unroll
    for (int o = 1; o < 32; o <<= 1) {
        int y = __shfl_up_sync(0xffffffffu, x, o);
        if (lane >= o) x += y;
    }
    if (lane == 31) wsum[w] = x;
    __syncthreads();
    if (w == 0) {
        int s = wsum[lane];
        #pragma unroll
        for (int o = 1; o < 32; o <<= 1) {
            int y = __shfl_up_sync(0xffffffffu, s, o);
            if (lane >= o) s += y;
        }
        wsum[lane] = s;
    }
    __syncthreads();
    int incl = x + (w ? wsum[w - 1] : 0);
    if (i < NN) g_scan[i] = incl;
    if (t == 1023) g_bsum[blockIdx.x] = incl;
}
__global__ void scan2_kernel() {   // scan 49 block sums -> exclusive
    int t = threadIdx.x;   // 64 threads, use 2 warps worth but simple shfl on 64
    __shared__ int sh[64];
    int v = (t < 49) ? g_bsum[t] : 0;
    sh[t] = v;
    __syncthreads();
    #pragma unroll
    for (int o = 1; o < 64; o <<= 1) {
        int x = (t >= o) ? sh[t - o] : 0;
        __syncthreads();
        sh[t] += x;
        __syncthreads();
    }
    if (t < 49) g_bsum[t] = sh[t] - v;
    if (t == 48) g_off[NN] = sh[48];
}
__global__ void scan3_kernel() {
    int i = blockIdx.x * blockDim.x + threadIdx.x;
    if (i >= NN) return;
    int cnt = g_off[i];
    int excl = g_bsum[i >> 10] + g_scan[i] - cnt;
    g_off[i] = excl;
    g_cur[i] = excl;
}
__global__ void fill_kernel(const int* __restrict__ src,
                            const int* __restrict__ dst,
                            const int* __restrict__ etype) {
    int e = blockIdx.x * blockDim.x + threadIdx.x;
    if (e >= EE) return;
    int d = dst[e];
    int pos = atomicAdd(&g_cur[d], 1);
    g_e2[pos] = make_uint2((unsigned)src[e] | ((unsigned)etype[e] << 17), (unsigned)d);
}

// ====== per-relation score: rs[r] = rel_emb[r]·(Wr^T a_r) + br·a_r ==========
__global__ void relscore_kernel(const float* __restrict__ rel_emb,
                                const float* __restrict__ Wr,
                                const float* __restrict__ br,
                                const float* __restrict__ attn) {
    __shared__ float v[DD];
    __shared__ float red[DD];
    const float* ar = attn + 2 * DD;
    int t = threadIdx.x;  // 128
    float acc = 0.f;
    #pragma unroll 4
    for (int d = 0; d < DD; d++) acc += Wr[d * DD + t] * ar[d];
    v[t] = acc;
    red[t] = br[t] * ar[t];
    __syncthreads();
    for (int s = 64; s > 0; s >>= 1) {
        if (t < s) red[t] += red[t + s];
        __syncthreads();
    }
    float c0 = red[0];
    int warp = t >> 5, lane = t & 31;
    for (int r = warp; r < RR; r += 4) {
        float p = 0.f;
        #pragma unroll
        for (int i = 0; i < 4; i++) p += rel_emb[r * DD + lane + 32 * i] * v[lane + 32 * i];
        #pragma unroll
        for (int o = 16; o; o >>= 1) p += __shfl_xor_sync(0xffffffffu, p, o);
        if (lane == 0) g_rs[r] = p + c0;
    }
}

// ====== tensor-core GEMM (mma.sync tf32, 3-term split) + bias + scores ======
#define LDPAD 132
__global__ __launch_bounds__(256, 1) void gemm_mma_kernel(
    const float* __restrict__ X, const int* __restrict__ idx,
    const float* __restrict__ W, const float* __restrict__ bias,
    const float* __restrict__ attn, float* __restrict__ hl) {
    extern __shared__ float sh[];
    float*    Xs  = sh;                       // 128*132 floats
    uint32_t* Whi = (uint32_t*)(sh + 128 * LDPAD);
    uint32_t* Wlo = Whi + 128 * LDPAD;

    int tid = threadIdx.x;
    int blockRow = blockIdx.x * 128;

    for (int i = tid; i < DD * DD; i += 256) {
        int j = i >> 7, k = i & 127;
        float w = W[i];
        uint32_t h = f2tf32(w);
        Whi[k * LDPAD + j] = h;
        Wlo[k * LDPAD + j] = f2tf32(w - __uint_as_float(h));
    }
    for (int i = tid; i < 128 * 32; i += 256) {
        int r = i >> 5, c = i & 31;
        int row = blockRow + r;
        float4 v = make_float4(0.f, 0.f, 0.f, 0.f);
        if (row < NN) {
            int g = idx ? idx[row] : row;
            v = ((const float4*)X)[(size_t)g * 32 + c];
        }
        *(float4*)&Xs[r * LDPAD + c * 4] = v;
    }
    __syncthreads();

    int wid = tid >> 5, lane = tid & 31;
    int gid = lane >> 2, tig = lane & 3;

    float acc[16][4];
    #pragma unroll
    for (int nt = 0; nt < 16; nt++)
        #pragma unroll
        for (int q = 0; q < 4; q++) acc[nt][q] = 0.f;

    const float* xa = &Xs[(wid * 16 + gid) * LDPAD];

    for (int k0 = 0; k0 < 16; k0++) {
        int kb = k0 * 8;
        float a0f = xa[kb + tig];
        float a1f = xa[8 * LDPAD + kb + tig];
        float a2f = xa[kb + tig + 4];
        float a3f = xa[8 * LDPAD + kb + tig + 4];
        uint32_t ahi[4], alo[4];
        ahi[0] = f2tf32(a0f); alo[0] = f2tf32(a0f - __uint_as_float(ahi[0]));
        ahi[1] = f2tf32(a1f); alo[1] = f2tf32(a1f - __uint_as_float(ahi[1]));
        ahi[2] = f2tf32(a2f); alo[2] = f2tf32(a2f - __uint_as_float(ahi[2]));
        ahi[3] = f2tf32(a3f); alo[3] = f2tf32(a3f - __uint_as_float(ahi[3]));

        const uint32_t* bh0 = Whi + (kb + tig) * LDPAD + gid;
        const uint32_t* bh1 = Whi + (kb + tig + 4) * LDPAD + gid;
        const uint32_t* bl0 = Wlo + (kb + tig) * LDPAD + gid;
        const uint32_t* bl1 = Wlo + (kb + tig + 4) * LDPAD + gid;

        #pragma unroll
        for (int nt = 0; nt < 16; nt++) {
            uint32_t bh[2] = { bh0[nt * 8], bh1[nt * 8] };
            uint32_t bl[2] = { bl0[nt * 8], bl1[nt * 8] };
            mma_tf32(acc[nt], ahi, bh);
            mma_tf32(acc[nt], alo, bh);
            mma_tf32(acc[nt], ahi, bl);
        }
    }

    int r0 = blockRow + wid * 16 + gid;
    int r1 = r0 + 8;
    float si0 = 0.f, sj0 = 0.f, si1 = 0.f, sj1 = 0.f;
    #pragma unroll
    for (int nt = 0; nt < 16; nt++) {
        int c0 = nt * 8 + tig * 2;
        float bb0 = bias[c0], bb1 = bias[c0 + 1];
        float v00 = acc[nt][0] + bb0, v01 = acc[nt][1] + bb1;
        float v10 = acc[nt][2] + bb0, v11 = acc[nt][3] + bb1;
        float ai0 = attn[c0], ai1 = attn[c0 + 1];
        float aj0 = attn[DD + c0], aj1 = attn[DD + c0 + 1];
        si0 += v00 * ai0 + v01 * ai1;
        sj0 += v00 * aj0 + v01 * aj1;
        si1 += v10 * ai0 + v11 * ai1;
        sj1 += v10 * aj0 + v11 * aj1;
        if (r0 < NN) *(float2*)&hl[(size_t)r0 * DD + c0] = make_float2(v00, v01);
        if (r1 < NN) *(float2*)&hl[(size_t)r1 * DD + c0] = make_float2(v10, v11);
    }
    #pragma unroll
    for (int o = 1; o <= 2; o <<= 1) {
        si0 += __shfl_xor_sync(0xffffffffu, si0, o);
        sj0 += __shfl_xor_sync(0xffffffffu, sj0, o);
        si1 += __shfl_xor_sync(0xffffffffu, si1, o);
        sj1 += __shfl_xor_sync(0xffffffffu, sj1, o);
    }
    if (tig == 0) {
        if (r0 < NN) { g_si[r0] = si0; g_sj[r0] = sj0; }
        if (r1 < NN) { g_si[r1] = si1; g_sj[r1] = sj1; }
    }
}

// ====== edge-parallel attention logit:  alpha = lrelu(si[d] + sj[s] + rs[ty]) =
__global__ void alpha_kernel() {
    int e = blockIdx.x * blockDim.x + threadIdx.x;
    if (e >= EE) return;
    uint2 p = g_e2[e];
    int s  = (int)(p.x & 0x1FFFFu);
    int ty = (int)(p.x >> 17);
    int d  = (int)p.y;
    float al = g_si[d] + g_sj[s] + g_rs[ty];
    g_alpha[e] = (al > 0.f) ? al : 0.2f * al;
}

// ====== warp-per-dst two-pass softmax aggregate + residual + LN + ReLU =======
__global__ void aggregate_kernel(const float* __restrict__ xin,
                                 const int* __restrict__ idx,
                                 const float* __restrict__ hl,
                                 const float* __restrict__ gamma,
                                 const float* __restrict__ beta,
                                 float* __restrict__ xout) {
    int w = (blockIdx.x * blockDim.x + threadIdx.x) >> 5;
    int lane = threadIdx.x & 31;
    if (w >= NN) return;

    int beg = g_off[w], end = g_off[w + 1];

    // pass 1: max over alphas (pure fmax chain; loads independent)
    float m = -3.402823466e38f;
    #pragma unroll 4
    for (int e = beg; e < end; e++) m = fmaxf(m, g_alpha[e]);

    // pass 2: accumulate exp(alpha-m) * hl[src]
    float den = 0.f;
    float ax = 0.f, ay = 0.f, az = 0.f, aw = 0.f;
    #pragma unroll 2
    for (int e = beg; e < end; e++) {
        float pe = __expf(g_alpha[e] - m);
        int s = (int)(g_e2[e].x & 0x1FFFFu);
        float4 h = *(const float4*)&hl[(size_t)s * DD + lane * 4];
        ax += pe * h.x;
        ay += pe * h.y;
        az += pe * h.z;
        aw += pe * h.w;
        den += pe;
    }
    float inv = (den > 0.f) ? (1.f / den) : 0.f;

    int xrow = idx ? idx[w] : w;
    float4 xi = *(const float4*)&xin[(size_t)xrow * DD + lane * 4];
    float yx = xi.x + ax * inv;
    float yy = xi.y + ay * inv;
    float yz = xi.z + az * inv;
    float yw = xi.w + aw * inv;

    float sum = yx + yy + yz + yw;
    #pragma unroll
    for (int o = 16; o; o >>= 1) sum += __shfl_xor_sync(0xffffffffu, sum, o);
    float mu = sum * (1.f / 128.f);
    float dx = yx - mu, dy = yy - mu, dz = yz - mu, dw = yw - mu;
    float sq = dx * dx + dy * dy + dz * dz + dw * dw;
    #pragma unroll
    for (int o = 16; o; o >>= 1) sq += __shfl_xor_sync(0xffffffffu, sq, o);
    float var = sq * (1.f / 128.f);
    float rsd = rsqrtf(var + EPS);

    float4 g4 = *(const float4*)&gamma[lane * 4];
    float4 b4 = *(const float4*)&beta[lane * 4];
    float4 o;
    o.x = fmaxf(0.f, dx * rsd * g4.x + b4.x);
    o.y = fmaxf(0.f, dy * rsd * g4.y + b4.y);
    o.z = fmaxf(0.f, dz * rsd * g4.z + b4.z);
    o.w = fmaxf(0.f, dw * rsd * g4.w + b4.w);
    *(float4*)&xout[(size_t)w * DD + lane * 4] = o;
}

// ---------------- launch ----------------
extern "C" void kernel_launch(void* const* d_in, const int* in_sizes, int n_in,
                              void* d_out, int out_size) {
    const int*   x_idx   = (const int*)  d_in[0];
    const int*   eidx    = (const int*)  d_in[1];
    const int*   etype   = (const int*)  d_in[2];
    const float* emb     = (const float*)d_in[3];
    const float* rel_emb = (const float*)d_in[4];
    const float* W1      = (const float*)d_in[5];
    const float* b1      = (const float*)d_in[6];
    const float* Wr1     = (const float*)d_in[7];
    const float* br1     = (const float*)d_in[8];
    const float* attn1   = (const float*)d_in[9];
    const float* g1      = (const float*)d_in[10];
    const float* be1     = (const float*)d_in[11];
    const float* W2      = (const float*)d_in[12];
    const float* b2      = (const float*)d_in[13];
    const float* Wr2     = (const float*)d_in[14];
    const float* br2     = (const float*)d_in[15];
    const float* attn2   = (const float*)d_in[16];
    const float* g2      = (const float*)d_in[17];
    const float* be2     = (const float*)d_in[18];
    float* out = (float*)d_out;

    const int* src = eidx;
    const int* dst = eidx + EE;

    float* phl = nullptr; cudaGetSymbolAddress((void**)&phl, g_hl);
    float* px2 = nullptr; cudaGetSymbolAddress((void**)&px2, g_x2);

    const int gemm_smem = 3 * 128 * LDPAD * (int)sizeof(float);   // 202752
    cudaFuncSetAttribute(gemm_mma_kernel,
                         cudaFuncAttributeMaxDynamicSharedMemorySize, gemm_smem);

    const int gemm_blocks = (NN + 127) / 128;          // 391
    const int warp_blocks = (NN * 32 + 255) / 256;
    const int edge_blocks = (EE + 255) / 256;

    zero_off_kernel<<<(NN + 256) / 256, 256>>>();
    count_kernel<<<edge_blocks, 256>>>(dst);
    scan1_kernel<<<(NN + 1023) / 1024, 1024>>>();
    gemm_mma_kernel<<<gemm_blocks, 256, gemm_smem>>>(emb, x_idx, W1, b1, attn1, phl);
    scan2_kernel<<<1, 64>>>();
    scan3_kernel<<<(NN + 255) / 256, 256>>>();
    fill_kernel<<<edge_blocks, 256>>>(src, dst, etype);
    relscore_kernel<<<1, 128>>>(rel_emb, Wr1, br1, attn1);

    alpha_kernel<<<edge_blocks, 256>>>();
    aggregate_kernel<<<warp_blocks, 256>>>(emb, x_idx, phl, g1, be1, px2);

    relscore_kernel<<<1, 128>>>(rel_emb, Wr2, br2, attn2);
    gemm_mma_kernel<<<gemm_blocks, 256, gemm_smem>>>(px2, nullptr, W2, b2, attn2, phl);
    alpha_kernel<<<edge_blocks, 256>>>();
    aggregate_kernel<<<warp_blocks, 256>>>(px2, nullptr, phl, g2, be2, out);
}

// round 5
// speedup vs baseline: 1.4243x; 1.1725x over previous
#include <cuda_runtime.h>
#include <cstdint>
#include <math.h>

#define NN 50000
#define EE 640000
#define DD 128
#define RR 100
#define EPS 1e-5f

// ---------------- device scratch ----------------
__device__ float    g_hl   [NN * DD];
__device__ float    g_x2   [NN * DD];
__device__ float    g_si   [NN];
__device__ float    g_sj   [NN];
__device__ float    g_rs   [RR];
__device__ int      g_off  [NN + 1];
__device__ int      g_cur  [NN];
__device__ int      g_scan [NN];
__device__ int      g_bsum [64];
__device__ uint2    g_e2   [EE];     // {src | (etype<<17), dst}, CSR order
__device__ float    g_alpha[EE];     // leaky-relu'd attention logit per edge

__device__ __forceinline__ uint32_t f2tf32(float x) {
    uint32_t r;
    asm("cvt.rna.tf32.f32 %0, %1;" : "=r"(r) : "f"(x));
    return r;
}

// m16n8k8 row.col tf32 MMA, D += A*B
__device__ __forceinline__ void mma_tf32(float* d, const uint32_t* a, const uint32_t* b) {
    asm volatile(
        "mma.sync.aligned.m16n8k8.row.col.f32.tf32.tf32.f32 "
        "{%0,%1,%2,%3}, {%4,%5,%6,%7}, {%8,%9}, {%0,%1,%2,%3};"
        : "+f"(d[0]), "+f"(d[1]), "+f"(d[2]), "+f"(d[3])
        : "r"(a[0]), "r"(a[1]), "r"(a[2]), "r"(a[3]), "r"(b[0]), "r"(b[1]));
}

// ================= CSR build =================
__global__ void zero_off_kernel() {
    int i = blockIdx.x * blockDim.x + threadIdx.x;
    if (i <= NN) g_off[i] = 0;
}
__global__ void count_kernel(const int* __restrict__ dst) {
    int e = blockIdx.x * blockDim.x + threadIdx.x;
    if (e < EE) atomicAdd(&g_off[dst[e]], 1);
}
// per-block (1024) inclusive scan via warp shuffles
__global__ void scan1_kernel() {
    __shared__ int wsum[32];
    int t = threadIdx.x, lane = t & 31, w = t >> 5;
    int i = blockIdx.x * 1024 + t;
    int v = (i < NN) ? g_off[i] : 0;
    int x = v;
    #pragma unroll
    for (int o = 1; o < 32; o <<= 1) {
        int y = __shfl_up_sync(0xffffffffu, x, o);
        if (lane >= o) x += y;
    }
    if (lane == 31) wsum[w] = x;
    __syncthreads();
    if (w == 0) {
        int s = wsum[lane];
        #pragma unroll
        for (int o = 1; o < 32; o <<= 1) {
            int y = __shfl_up_sync(0xffffffffu, s, o);
            if (lane >= o) s += y;
        }
        wsum[lane] = s;
    }
    __syncthreads();
    int incl = x + (w ? wsum[w - 1] : 0);
    if (i < NN) g_scan[i] = incl;
    if (t == 1023) g_bsum[blockIdx.x] = incl;
}
__global__ void scan2_kernel() {   // scan 49 block sums -> exclusive
    int t = threadIdx.x;   // 64 threads
    __shared__ int sh[64];
    int v = (t < 49) ? g_bsum[t] : 0;
    sh[t] = v;
    __syncthreads();
    #pragma unroll
    for (int o = 1; o < 64; o <<= 1) {
        int x = (t >= o) ? sh[t - o] : 0;
        __syncthreads();
        sh[t] += x;
        __syncthreads();
    }
    if (t < 49) g_bsum[t] = sh[t] - v;
    if (t == 48) g_off[NN] = sh[48];
}
__global__ void scan3_kernel() {
    int i = blockIdx.x * blockDim.x + threadIdx.x;
    if (i >= NN) return;
    int cnt = g_off[i];
    int excl = g_bsum[i >> 10] + g_scan[i] - cnt;
    g_off[i] = excl;
    g_cur[i] = excl;
}
__global__ void fill_kernel(const int* __restrict__ src,
                            const int* __restrict__ dst,
                            const int* __restrict__ etype) {
    int e = blockIdx.x * blockDim.x + threadIdx.x;
    if (e >= EE) return;
    int d = dst[e];
    int pos = atomicAdd(&g_cur[d], 1);
    g_e2[pos] = make_uint2((unsigned)src[e] | ((unsigned)etype[e] << 17), (unsigned)d);
}

// ====== per-relation score: rs[r] = rel_emb[r]·(Wr^T a_r) + br·a_r ==========
__global__ void relscore_kernel(const float* __restrict__ rel_emb,
                                const float* __restrict__ Wr,
                                const float* __restrict__ br,
                                const float* __restrict__ attn) {
    __shared__ float v[DD];
    __shared__ float red[DD];
    const float* ar = attn + 2 * DD;
    int t = threadIdx.x;  // 128
    float acc = 0.f;
    #pragma unroll 4
    for (int d = 0; d < DD; d++) acc += Wr[d * DD + t] * ar[d];
    v[t] = acc;
    red[t] = br[t] * ar[t];
    __syncthreads();
    for (int s = 64; s > 0; s >>= 1) {
        if (t < s) red[t] += red[t + s];
        __syncthreads();
    }
    float c0 = red[0];
    int warp = t >> 5, lane = t & 31;
    for (int r = warp; r < RR; r += 4) {
        float p = 0.f;
        #pragma unroll
        for (int i = 0; i < 4; i++) p += rel_emb[r * DD + lane + 32 * i] * v[lane + 32 * i];
        #pragma unroll
        for (int o = 16; o; o >>= 1) p += __shfl_xor_sync(0xffffffffu, p, o);
        if (lane == 0) g_rs[r] = p + c0;
    }
}

// ====== tensor-core GEMM (mma.sync tf32, 3-term split) + bias + scores ======
// 512 threads, 128 rows/CTA. Warp w: rows (w>>1)*16, cols (w&1)*64.
// W stored in smem in MMA-fragment order for vectorized ld.shared.v4.
#define LDPAD 132
__global__ __launch_bounds__(512, 1) void gemm_mma_kernel(
    const float* __restrict__ X, const int* __restrict__ idx,
    const float* __restrict__ W, const float* __restrict__ bias,
    const float* __restrict__ attn, float* __restrict__ hl) {
    extern __shared__ float sh[];
    float*    Xs  = sh;                                 // [128][132] fp32
    uint32_t* Whi = (uint32_t*)(sh + 128 * LDPAD);      // 16384 u32 frag-order
    uint32_t* Wlo = Whi + 16384;                        // 16384 u32
    float*    sSi = (float*)(Wlo + 16384);              // [128][2]
    float*    sSj = sSi + 256;                          // [128][2]

    int tid = threadIdx.x;
    int blockRow = blockIdx.x * 128;

    // W[j][k] -> fragment-order smem, split hi/lo tf32.
    // b0 of n-tile nt: element [n=nt*8+gid][k=k0*8+tig]; b1: k+4.
    // uint4 at [(k0*8+np)*32 + gid*4+tig]: {b0(2np), b1(2np), b0(2np+1), b1(2np+1)}
    for (int i = tid; i < DD * DD; i += 512) {
        int j = i >> 7, k = i & 127;
        float w = W[i];
        uint32_t h = f2tf32(w);
        uint32_t l = f2tf32(w - __uint_as_float(h));
        int nt = j >> 3, gd = j & 7;
        int k0 = k >> 3, kin = k & 7, tg = kin & 3, half = kin >> 2;
        int off = (((k0 * 8 + (nt >> 1)) * 32) + gd * 4 + tg) * 4 + ((nt & 1) * 2 + half);
        Whi[off] = h;
        Wlo[off] = l;
    }
    // X tile (gathered)
    for (int i = tid; i < 128 * 32; i += 512) {
        int r = i >> 5, c = i & 31;
        int row = blockRow + r;
        float4 v = make_float4(0.f, 0.f, 0.f, 0.f);
        if (row < NN) {
            int g = idx ? idx[row] : row;
            v = ((const float4*)X)[(size_t)g * 32 + c];
        }
        *(float4*)&Xs[r * LDPAD + c * 4] = v;
    }
    __syncthreads();

    int w = tid >> 5, lane = tid & 31;
    int wr = w >> 1, wc = w & 1;
    int gid = lane >> 2, tig = lane & 3;

    float acc[8][4];
    #pragma unroll
    for (int nt = 0; nt < 8; nt++)
        #pragma unroll
        for (int q = 0; q < 4; q++) acc[nt][q] = 0.f;

    const float* xa = &Xs[(wr * 16 + gid) * LDPAD];
    const uint4* WhiV = (const uint4*)Whi;
    const uint4* WloV = (const uint4*)Wlo;

    for (int k0 = 0; k0 < 16; k0++) {
        int kb = k0 * 8;
        float a0f = xa[kb + tig];
        float a1f = xa[8 * LDPAD + kb + tig];
        float a2f = xa[kb + tig + 4];
        float a3f = xa[8 * LDPAD + kb + tig + 4];
        uint32_t ahi[4], alo[4];
        ahi[0] = f2tf32(a0f); alo[0] = f2tf32(a0f - __uint_as_float(ahi[0]));
        ahi[1] = f2tf32(a1f); alo[1] = f2tf32(a1f - __uint_as_float(ahi[1]));
        ahi[2] = f2tf32(a2f); alo[2] = f2tf32(a2f - __uint_as_float(ahi[2]));
        ahi[3] = f2tf32(a3f); alo[3] = f2tf32(a3f - __uint_as_float(ahi[3]));

        #pragma unroll
        for (int npl = 0; npl < 4; npl++) {
            int np = wc * 4 + npl;
            uint4 bh = WhiV[(k0 * 8 + np) * 32 + lane];
            uint4 bl = WloV[(k0 * 8 + np) * 32 + lane];
            uint32_t bhA[2] = { bh.x, bh.y }, bhB[2] = { bh.z, bh.w };
            uint32_t blA[2] = { bl.x, bl.y }, blB[2] = { bl.z, bl.w };
            mma_tf32(acc[npl * 2],     ahi, bhA);
            mma_tf32(acc[npl * 2],     alo, bhA);
            mma_tf32(acc[npl * 2],     ahi, blA);
            mma_tf32(acc[npl * 2 + 1], ahi, bhB);
            mma_tf32(acc[npl * 2 + 1], alo, bhB);
            mma_tf32(acc[npl * 2 + 1], ahi, blB);
        }
    }

    // epilogue: bias, store hl, partial attention scores for this col-half
    int r0l = wr * 16 + gid, r1l = r0l + 8;
    int r0 = blockRow + r0l, r1 = blockRow + r1l;
    float si0 = 0.f, sj0 = 0.f, si1 = 0.f, sj1 = 0.f;
    #pragma unroll
    for (int ntl = 0; ntl < 8; ntl++) {
        int c0 = wc * 64 + ntl * 8 + tig * 2;
        float bb0 = bias[c0], bb1 = bias[c0 + 1];
        float v00 = acc[ntl][0] + bb0, v01 = acc[ntl][1] + bb1;
        float v10 = acc[ntl][2] + bb0, v11 = acc[ntl][3] + bb1;
        float ai0 = attn[c0], ai1 = attn[c0 + 1];
        float aj0 = attn[DD + c0], aj1 = attn[DD + c0 + 1];
        si0 += v00 * ai0 + v01 * ai1;
        sj0 += v00 * aj0 + v01 * aj1;
        si1 += v10 * ai0 + v11 * ai1;
        sj1 += v10 * aj0 + v11 * aj1;
        if (r0 < NN) *(float2*)&hl[(size_t)r0 * DD + c0] = make_float2(v00, v01);
        if (r1 < NN) *(float2*)&hl[(size_t)r1 * DD + c0] = make_float2(v10, v11);
    }
    #pragma unroll
    for (int o = 1; o <= 2; o <<= 1) {
        si0 += __shfl_xor_sync(0xffffffffu, si0, o);
        sj0 += __shfl_xor_sync(0xffffffffu, sj0, o);
        si1 += __shfl_xor_sync(0xffffffffu, si1, o);
        sj1 += __shfl_xor_sync(0xffffffffu, sj1, o);
    }
    if (tig == 0) {
        sSi[r0l * 2 + wc] = si0; sSj[r0l * 2 + wc] = sj0;
        sSi[r1l * 2 + wc] = si1; sSj[r1l * 2 + wc] = sj1;
    }
    __syncthreads();
    if (tid < 128) {
        int row = blockRow + tid;
        if (row < NN) {
            g_si[row] = sSi[tid * 2] + sSi[tid * 2 + 1];
            g_sj[row] = sSj[tid * 2] + sSj[tid * 2 + 1];
        }
    }
}

// ====== edge-parallel attention logit:  alpha = lrelu(si[d] + sj[s] + rs[ty]) =
__global__ void alpha_kernel() {
    int e = blockIdx.x * blockDim.x + threadIdx.x;
    if (e >= EE) return;
    uint2 p = g_e2[e];
    int s  = (int)(p.x & 0x1FFFFu);
    int ty = (int)(p.x >> 17);
    int d  = (int)p.y;
    float al = g_si[d] + g_sj[s] + g_rs[ty];
    g_alpha[e] = (al > 0.f) ? al : 0.2f * al;
}

// ====== warp-per-dst two-pass softmax aggregate + residual + LN + ReLU =======
__global__ void aggregate_kernel(const float* __restrict__ xin,
                                 const int* __restrict__ idx,
                                 const float* __restrict__ hl,
                                 const float* __restrict__ gamma,
                                 const float* __restrict__ beta,
                                 float* __restrict__ xout) {
    int w = (blockIdx.x * blockDim.x + threadIdx.x) >> 5;
    int lane = threadIdx.x & 31;
    if (w >= NN) return;

    int beg = g_off[w], end = g_off[w + 1];

    float m = -3.402823466e38f;
    #pragma unroll 4
    for (int e = beg; e < end; e++) m = fmaxf(m, g_alpha[e]);

    float den = 0.f;
    float ax = 0.f, ay = 0.f, az = 0.f, aw = 0.f;
    #pragma unroll 2
    for (int e = beg; e < end; e++) {
        float pe = __expf(g_alpha[e] - m);
        int s = (int)(g_e2[e].x & 0x1FFFFu);
        float4 h = *(const float4*)&hl[(size_t)s * DD + lane * 4];
        ax += pe * h.x;
        ay += pe * h.y;
        az += pe * h.z;
        aw += pe * h.w;
        den += pe;
    }
    float inv = (den > 0.f) ? (1.f / den) : 0.f;

    int xrow = idx ? idx[w] : w;
    float4 xi = *(const float4*)&xin[(size_t)xrow * DD + lane * 4];
    float yx = xi.x + ax * inv;
    float yy = xi.y + ay * inv;
    float yz = xi.z + az * inv;
    float yw = xi.w + aw * inv;

    float sum = yx + yy + yz + yw;
    #pragma unroll
    for (int o = 16; o; o >>= 1) sum += __shfl_xor_sync(0xffffffffu, sum, o);
    float mu = sum * (1.f / 128.f);
    float dx = yx - mu, dy = yy - mu, dz = yz - mu, dw = yw - mu;
    float sq = dx * dx + dy * dy + dz * dz + dw * dw;
    #pragma unroll
    for (int o = 16; o; o >>= 1) sq += __shfl_xor_sync(0xffffffffu, sq, o);
    float var = sq * (1.f / 128.f);
    float rsd = rsqrtf(var + EPS);

    float4 g4 = *(const float4*)&gamma[lane * 4];
    float4 b4 = *(const float4*)&beta[lane * 4];
    float4 o;
    o.x = fmaxf(0.f, dx * rsd * g4.x + b4.x);
    o.y = fmaxf(0.f, dy * rsd * g4.y + b4.y);
    o.z = fmaxf(0.f, dz * rsd * g4.z + b4.z);
    o.w = fmaxf(0.f, dw * rsd * g4.w + b4.w);
    *(float4*)&xout[(size_t)w * DD + lane * 4] = o;
}

// ---------------- launch ----------------
extern "C" void kernel_launch(void* const* d_in, const int* in_sizes, int n_in,
                              void* d_out, int out_size) {
    const int*   x_idx   = (const int*)  d_in[0];
    const int*   eidx    = (const int*)  d_in[1];
    const int*   etype   = (const int*)  d_in[2];
    const float* emb     = (const float*)d_in[3];
    const float* rel_emb = (const float*)d_in[4];
    const float* W1      = (const float*)d_in[5];
    const float* b1      = (const float*)d_in[6];
    const float* Wr1     = (const float*)d_in[7];
    const float* br1     = (const float*)d_in[8];
    const float* attn1   = (const float*)d_in[9];
    const float* g1      = (const float*)d_in[10];
    const float* be1     = (const float*)d_in[11];
    const float* W2      = (const float*)d_in[12];
    const float* b2      = (const float*)d_in[13];
    const float* Wr2     = (const float*)d_in[14];
    const float* br2     = (const float*)d_in[15];
    const float* attn2   = (const float*)d_in[16];
    const float* g2      = (const float*)d_in[17];
    const float* be2     = (const float*)d_in[18];
    float* out = (float*)d_out;

    const int* src = eidx;
    const int* dst = eidx + EE;

    float* phl = nullptr; cudaGetSymbolAddress((void**)&phl, g_hl);
    float* px2 = nullptr; cudaGetSymbolAddress((void**)&px2, g_x2);

    // Xs + Whi + Wlo + sSi + sSj
    const int gemm_smem = (128 * LDPAD + 16384 + 16384 + 256 + 256) * (int)sizeof(float);
    cudaFuncSetAttribute(gemm_mma_kernel,
                         cudaFuncAttributeMaxDynamicSharedMemorySize, gemm_smem);

    const int gemm_blocks = (NN + 127) / 128;          // 391
    const int warp_blocks = (NN * 32 + 255) / 256;
    const int edge_blocks = (EE + 255) / 256;

    zero_off_kernel<<<(NN + 256) / 256, 256>>>();
    count_kernel<<<edge_blocks, 256>>>(dst);
    scan1_kernel<<<(NN + 1023) / 1024, 1024>>>();
    gemm_mma_kernel<<<gemm_blocks, 512, gemm_smem>>>(emb, x_idx, W1, b1, attn1, phl);
    scan2_kernel<<<1, 64>>>();
    scan3_kernel<<<(NN + 255) / 256, 256>>>();
    fill_kernel<<<edge_blocks, 256>>>(src, dst, etype);
    relscore_kernel<<<1, 128>>>(rel_emb, Wr1, br1, attn1);

    alpha_kernel<<<edge_blocks, 256>>>();
    aggregate_kernel<<<warp_blocks, 256>>>(emb, x_idx, phl, g1, be1, px2);

    relscore_kernel<<<1, 128>>>(rel_emb, Wr2, br2, attn2);
    gemm_mma_kernel<<<gemm_blocks, 512, gemm_smem>>>(px2, nullptr, W2, b2, attn2, phl);
    alpha_kernel<<<edge_blocks, 256>>>();
    aggregate_kernel<<<warp_blocks, 256>>>(px2, nullptr, phl, g2, be2, out);
}

// round 7
// speedup vs baseline: 1.6202x; 1.1375x over previous
#include <cuda_runtime.h>
#include <cuda_bf16.h>
#include <cstdint>
#include <math.h>

#define NN 50000
#define EE 640000
#define DD 128
#define RR 100
#define EPS 1e-5f

// ---------------- device scratch ----------------
__device__ float    g_hl   [NN * DD];
__device__ float    g_x2   [NN * DD];
__device__ float    g_si   [NN];
__device__ float    g_sj   [NN];
__device__ float    g_rs   [RR];
__device__ int      g_off  [NN + 1];
__device__ int      g_cur  [NN];
__device__ int      g_scan [NN];
__device__ int      g_bsum [64];
__device__ uint2    g_e2   [EE];     // {src | (etype<<17), dst}, CSR order
__device__ float    g_alpha[EE];     // leaky-relu'd attention logit per edge

// m16n8k16 row.col bf16 MMA, D += A*B
__device__ __forceinline__ void mma_bf16(float* d, const uint32_t* a, uint32_t b0, uint32_t b1) {
    asm volatile(
        "mma.sync.aligned.m16n8k16.row.col.f32.bf16.bf16.f32 "
        "{%0,%1,%2,%3}, {%4,%5,%6,%7}, {%8,%9}, {%0,%1,%2,%3};"
        : "+f"(d[0]), "+f"(d[1]), "+f"(d[2]), "+f"(d[3])
        : "r"(a[0]), "r"(a[1]), "r"(a[2]), "r"(a[3]), "r"(b0), "r"(b1));
}

__device__ __forceinline__ uint32_t pack_bf16(float x0, float x1) {
    __nv_bfloat162 h = __floats2bfloat162_rn(x0, x1);
    return *(uint32_t*)&h;
}
__device__ __forceinline__ float bf16_hi_f(float x) {
    return __bfloat162float(__float2bfloat16(x));
}

// ================= CSR build =================
__global__ void zero_off_kernel() {
    int i = blockIdx.x * blockDim.x + threadIdx.x;
    if (i <= NN) g_off[i] = 0;
}
__global__ void count_kernel(const int* __restrict__ dst) {
    int e = blockIdx.x * blockDim.x + threadIdx.x;
    if (e < EE) atomicAdd(&g_off[dst[e]], 1);
}
__global__ void scan1_kernel() {
    __shared__ int wsum[32];
    int t = threadIdx.x, lane = t & 31, w = t >> 5;
    int i = blockIdx.x * 1024 + t;
    int v = (i < NN) ? g_off[i] : 0;
    int x = v;
    #pragma unroll
    for (int o = 1; o < 32; o <<= 1) {
        int y = __shfl_up_sync(0xffffffffu, x, o);
        if (lane >= o) x += y;
    }
    if (lane == 31) wsum[w] = x;
    __syncthreads();
    if (w == 0) {
        int s = wsum[lane];
        #pragma unroll
        for (int o = 1; o < 32; o <<= 1) {
            int y = __shfl_up_sync(0xffffffffu, s, o);
            if (lane >= o) s += y;
        }
        wsum[lane] = s;
    }
    __syncthreads();
    int incl = x + (w ? wsum[w - 1] : 0);
    if (i < NN) g_scan[i] = incl;
    if (t == 1023) g_bsum[blockIdx.x] = incl;
}
__global__ void scan2_kernel() {
    int t = threadIdx.x;   // 64 threads
    __shared__ int sh[64];
    int v = (t < 49) ? g_bsum[t] : 0;
    sh[t] = v;
    __syncthreads();
    #pragma unroll
    for (int o = 1; o < 64; o <<= 1) {
        int x = (t >= o) ? sh[t - o] : 0;
        __syncthreads();
        sh[t] += x;
        __syncthreads();
    }
    if (t < 49) g_bsum[t] = sh[t] - v;
    if (t == 48) g_off[NN] = sh[48];
}
__global__ void scan3_kernel() {
    int i = blockIdx.x * blockDim.x + threadIdx.x;
    if (i >= NN) return;
    int cnt = g_off[i];
    int excl = g_bsum[i >> 10] + g_scan[i] - cnt;
    g_off[i] = excl;
    g_cur[i] = excl;
}
__global__ void fill_kernel(const int* __restrict__ src,
                            const int* __restrict__ dst,
                            const int* __restrict__ etype) {
    int e = blockIdx.x * blockDim.x + threadIdx.x;
    if (e >= EE) return;
    int d = dst[e];
    int pos = atomicAdd(&g_cur[d], 1);
    g_e2[pos] = make_uint2((unsigned)src[e] | ((unsigned)etype[e] << 17), (unsigned)d);
}

// ====== per-relation score: rs[r] = rel_emb[r]·(Wr^T a_r) + br·a_r ==========
__global__ void relscore_kernel(const float* __restrict__ rel_emb,
                                const float* __restrict__ Wr,
                                const float* __restrict__ br,
                                const float* __restrict__ attn) {
    __shared__ float v[DD];
    __shared__ float red[DD];
    const float* ar = attn + 2 * DD;
    int t = threadIdx.x;  // 128
    float acc = 0.f;
    #pragma unroll 4
    for (int d = 0; d < DD; d++) acc += Wr[d * DD + t] * ar[d];
    v[t] = acc;
    red[t] = br[t] * ar[t];
    __syncthreads();
    for (int s = 64; s > 0; s >>= 1) {
        if (t < s) red[t] += red[t + s];
        __syncthreads();
    }
    float c0 = red[0];
    int warp = t >> 5, lane = t & 31;
    for (int r = warp; r < RR; r += 4) {
        float p = 0.f;
        #pragma unroll
        for (int i = 0; i < 4; i++) p += rel_emb[r * DD + lane + 32 * i] * v[lane + 32 * i];
        #pragma unroll
        for (int o = 16; o; o >>= 1) p += __shfl_xor_sync(0xffffffffu, p, o);
        if (lane == 0) g_rs[r] = p + c0;
    }
}

// ====== tensor-core GEMM (mma.sync bf16 m16n8k16, 3-term split) =============
// 1024 threads, 128 rows/CTA. Warp w: rows (w>>2)*16, cols (w&3)*32.
// A and W pre-packed in MMA-fragment order (uint4 per lane) in smem.
// smem u32 layout: AFhi[8192] AFlo[8192] WFhi[8192] WFlo[8192] sSi[512] sSj[512]
__global__ __launch_bounds__(1024, 1) void gemm_mma_kernel(
    const float* __restrict__ X, const int* __restrict__ idx,
    const float* __restrict__ W, const float* __restrict__ bias,
    const float* __restrict__ attn, float* __restrict__ hl) {
    extern __shared__ uint32_t su[];
    uint32_t* AFhi = su;
    uint32_t* AFlo = su + 8192;
    uint32_t* WFhi = su + 16384;
    uint32_t* WFlo = su + 24576;
    float*    sSi  = (float*)(su + 32768);
    float*    sSj  = sSi + 512;

    int tid = threadIdx.x;
    int blockRow = blockIdx.x * 128;

    // ---- load X (gathered) -> A fragments (hi/lo bf16 pairs) ----
    // fragment u32 index for (row, kp):  kp = k/2
    //   k0=kp>>3, tig=kp&3, khalf=(kp>>2)&1, gid=row&7, rbit=(row>>3)&1, wr=row>>4
    //   off = ((k0*8+wr)*32 + gid*4 + tig)*4 + (rbit + 2*khalf)
    for (int i = tid; i < 128 * 32; i += 1024) {
        int r = i >> 5, c4 = i & 31;           // float4 index; k = c4*4
        int row = blockRow + r;
        float4 v = make_float4(0.f, 0.f, 0.f, 0.f);
        if (row < NN) {
            int g = idx ? idx[row] : row;
            v = ((const float4*)X)[(size_t)g * 32 + c4];
        }
        int gid = r & 7, rbit = (r >> 3) & 1, wr = r >> 4;
        #pragma unroll
        for (int p = 0; p < 2; p++) {
            int kp = c4 * 2 + p;
            float x0 = p ? v.z : v.x;
            float x1 = p ? v.w : v.y;
            float h0 = bf16_hi_f(x0), h1 = bf16_hi_f(x1);
            int k0 = kp >> 3, tig = kp & 3, khalf = (kp >> 2) & 1;
            int off = ((k0 * 8 + wr) * 32 + gid * 4 + tig) * 4 + rbit + 2 * khalf;
            AFhi[off] = pack_bf16(x0, x1);
            AFlo[off] = pack_bf16(x0 - h0, x1 - h1);
        }
    }
    // ---- load W -> B fragments ----
    // for (n=j, kp): nt=n>>3, gd=n&7, np=nt>>1, h=nt&1
    //   off = ((k0*8+np)*32 + gd*4 + tig)*4 + (h*2 + khalf)
    for (int i = tid; i < 128 * 32; i += 1024) {
        int j = i >> 5, c4 = i & 31;
        float4 v = ((const float4*)W)[(size_t)j * 32 + c4];
        int nt = j >> 3, gd = j & 7, np = nt >> 1, hh = nt & 1;
        #pragma unroll
        for (int p = 0; p < 2; p++) {
            int kp = c4 * 2 + p;
            float x0 = p ? v.z : v.x;
            float x1 = p ? v.w : v.y;
            float h0 = bf16_hi_f(x0), h1 = bf16_hi_f(x1);
            int k0 = kp >> 3, tig = kp & 3, khalf = (kp >> 2) & 1;
            int off = ((k0 * 8 + np) * 32 + gd * 4 + tig) * 4 + hh * 2 + khalf;
            WFhi[off] = pack_bf16(x0, x1);
            WFlo[off] = pack_bf16(x0 - h0, x1 - h1);
        }
    }
    __syncthreads();

    int w = tid >> 5, lane = tid & 31;
    int wr = w >> 2, wc = w & 3;
    int gid = lane >> 2, tig = lane & 3;

    float acc[4][4];
    #pragma unroll
    for (int nt = 0; nt < 4; nt++)
        #pragma unroll
        for (int q = 0; q < 4; q++) acc[nt][q] = 0.f;

    const uint4* AH = (const uint4*)AFhi;
    const uint4* AL = (const uint4*)AFlo;
    const uint4* WH = (const uint4*)WFhi;
    const uint4* WL = (const uint4*)WFlo;

    #pragma unroll
    for (int k0 = 0; k0 < 8; k0++) {
        uint4 ahv = AH[(k0 * 8 + wr) * 32 + lane];
        uint4 alv = AL[(k0 * 8 + wr) * 32 + lane];
        uint32_t ah[4] = { ahv.x, ahv.y, ahv.z, ahv.w };
        uint32_t al[4] = { alv.x, alv.y, alv.z, alv.w };
        #pragma unroll
        for (int npl = 0; npl < 2; npl++) {
            int np = wc * 2 + npl;
            uint4 bh = WH[(k0 * 8 + np) * 32 + lane];
            uint4 bl = WL[(k0 * 8 + np) * 32 + lane];
            mma_bf16(acc[npl * 2],     ah, bh.x, bh.y);
            mma_bf16(acc[npl * 2],     al, bh.x, bh.y);
            mma_bf16(acc[npl * 2],     ah, bl.x, bl.y);
            mma_bf16(acc[npl * 2 + 1], ah, bh.z, bh.w);
            mma_bf16(acc[npl * 2 + 1], al, bh.z, bh.w);
            mma_bf16(acc[npl * 2 + 1], ah, bl.z, bl.w);
        }
    }

    // epilogue: bias, store hl, partial attention scores for this col quarter
    int r0l = wr * 16 + gid, r1l = r0l + 8;
    int r0 = blockRow + r0l, r1 = blockRow + r1l;
    float si0 = 0.f, sj0 = 0.f, si1 = 0.f, sj1 = 0.f;
    #pragma unroll
    for (int ntl = 0; ntl < 4; ntl++) {
        int c0 = wc * 32 + ntl * 8 + tig * 2;
        float bb0 = bias[c0], bb1 = bias[c0 + 1];
        float v00 = acc[ntl][0] + bb0, v01 = acc[ntl][1] + bb1;
        float v10 = acc[ntl][2] + bb0, v11 = acc[ntl][3] + bb1;
        float ai0 = attn[c0], ai1 = attn[c0 + 1];
        float aj0 = attn[DD + c0], aj1 = attn[DD + c0 + 1];
        si0 += v00 * ai0 + v01 * ai1;
        sj0 += v00 * aj0 + v01 * aj1;
        si1 += v10 * ai0 + v11 * ai1;
        sj1 += v10 * aj0 + v11 * aj1;
        if (r0 < NN) *(float2*)&hl[(size_t)r0 * DD + c0] = make_float2(v00, v01);
        if (r1 < NN) *(float2*)&hl[(size_t)r1 * DD + c0] = make_float2(v10, v11);
    }
    #pragma unroll
    for (int o = 1; o <= 2; o <<= 1) {
        si0 += __shfl_xor_sync(0xffffffffu, si0, o);
        sj0 += __shfl_xor_sync(0xffffffffu, sj0, o);
        si1 += __shfl_xor_sync(0xffffffffu, si1, o);
        sj1 += __shfl_xor_sync(0xffffffffu, sj1, o);
    }
    if (tig == 0) {
        sSi[r0l * 4 + wc] = si0; sSj[r0l * 4 + wc] = sj0;
        sSi[r1l * 4 + wc] = si1; sSj[r1l * 4 + wc] = sj1;
    }
    __syncthreads();
    if (tid < 128) {
        int row = blockRow + tid;
        if (row < NN) {
            g_si[row] = sSi[tid * 4] + sSi[tid * 4 + 1] + sSi[tid * 4 + 2] + sSi[tid * 4 + 3];
            g_sj[row] = sSj[tid * 4] + sSj[tid * 4 + 1] + sSj[tid * 4 + 2] + sSj[tid * 4 + 3];
        }
    }
}

// ====== edge-parallel attention logit ======
__global__ void alpha_kernel() {
    int e = blockIdx.x * blockDim.x + threadIdx.x;
    if (e >= EE) return;
    uint2 p = g_e2[e];
    int s  = (int)(p.x & 0x1FFFFu);
    int ty = (int)(p.x >> 17);
    int d  = (int)p.y;
    float al = g_si[d] + g_sj[s] + g_rs[ty];
    g_alpha[e] = (al > 0.f) ? al : 0.2f * al;
}

// ====== warp-per-dst two-pass softmax aggregate + residual + LN + ReLU =======
__global__ void aggregate_kernel(const float* __restrict__ xin,
                                 const int* __restrict__ idx,
                                 const float* __restrict__ hl,
                                 const float* __restrict__ gamma,
                                 const float* __restrict__ beta,
                                 float* __restrict__ xout) {
    int w = (blockIdx.x * blockDim.x + threadIdx.x) >> 5;
    int lane = threadIdx.x & 31;
    if (w >= NN) return;

    int beg = g_off[w], end = g_off[w + 1];

    float m = -3.402823466e38f;
    #pragma unroll 4
    for (int e = beg; e < end; e++) m = fmaxf(m, g_alpha[e]);

    float den = 0.f;
    float ax = 0.f, ay = 0.f, az = 0.f, aw = 0.f;
    #pragma unroll 2
    for (int e = beg; e < end; e++) {
        float pe = __expf(g_alpha[e] - m);
        int s = (int)(g_e2[e].x & 0x1FFFFu);
        float4 h = *(const float4*)&hl[(size_t)s * DD + lane * 4];
        ax += pe * h.x;
        ay += pe * h.y;
        az += pe * h.z;
        aw += pe * h.w;
        den += pe;
    }
    float inv = (den > 0.f) ? (1.f / den) : 0.f;

    int xrow = idx ? idx[w] : w;
    float4 xi = *(const float4*)&xin[(size_t)xrow * DD + lane * 4];
    float yx = xi.x + ax * inv;
    float yy = xi.y + ay * inv;
    float yz = xi.z + az * inv;
    float yw = xi.w + aw * inv;

    float sum = yx + yy + yz + yw;
    #pragma unroll
    for (int o = 16; o; o >>= 1) sum += __shfl_xor_sync(0xffffffffu, sum, o);
    float mu = sum * (1.f / 128.f);
    float dx = yx - mu, dy = yy - mu, dz = yz - mu, dw = yw - mu;
    float sq = dx * dx + dy * dy + dz * dz + dw * dw;
    #pragma unroll
    for (int o = 16; o; o >>= 1) sq += __shfl_xor_sync(0xffffffffu, sq, o);
    float var = sq * (1.f / 128.f);
    float rsd = rsqrtf(var + EPS);

    float4 g4 = *(const float4*)&gamma[lane * 4];
    float4 b4 = *(const float4*)&beta[lane * 4];
    float4 o;
    o.x = fmaxf(0.f, dx * rsd * g4.x + b4.x);
    o.y = fmaxf(0.f, dy * rsd * g4.y + b4.y);
    o.z = fmaxf(0.f, dz * rsd * g4.z + b4.z);
    o.w = fmaxf(0.f, dw * rsd * g4.w + b4.w);
    *(float4*)&xout[(size_t)w * DD + lane * 4] = o;
}

// ---------------- launch ----------------
extern "C" void kernel_launch(void* const* d_in, const int* in_sizes, int n_in,
                              void* d_out, int out_size) {
    const int*   x_idx   = (const int*)  d_in[0];
    const int*   eidx    = (const int*)  d_in[1];
    const int*   etype   = (const int*)  d_in[2];
    const float* emb     = (const float*)d_in[3];
    const float* rel_emb = (const float*)d_in[4];
    const float* W1      = (const float*)d_in[5];
    const float* b1      = (const float*)d_in[6];
    const float* Wr1     = (const float*)d_in[7];
    const float* br1     = (const float*)d_in[8];
    const float* attn1   = (const float*)d_in[9];
    const float* g1      = (const float*)d_in[10];
    const float* be1     = (const float*)d_in[11];
    const float* W2      = (const float*)d_in[12];
    const float* b2      = (const float*)d_in[13];
    const float* Wr2     = (const float*)d_in[14];
    const float* br2     = (const float*)d_in[15];
    const float* attn2   = (const float*)d_in[16];
    const float* g2      = (const float*)d_in[17];
    const float* be2     = (const float*)d_in[18];
    float* out = (float*)d_out;

    const int* src = eidx;
    const int* dst = eidx + EE;

    float* phl = nullptr; cudaGetSymbolAddress((void**)&phl, g_hl);
    float* px2 = nullptr; cudaGetSymbolAddress((void**)&px2, g_x2);

    const int gemm_smem = (32768 + 1024) * (int)sizeof(uint32_t);   // 135168
    cudaFuncSetAttribute(gemm_mma_kernel,
                         cudaFuncAttributeMaxDynamicSharedMemorySize, gemm_smem);

    const int gemm_blocks = (NN + 127) / 128;          // 391
    const int warp_blocks = (NN * 32 + 255) / 256;
    const int edge_blocks = (EE + 255) / 256;

    zero_off_kernel<<<(NN + 256) / 256, 256>>>();
    count_kernel<<<edge_blocks, 256>>>(dst);
    scan1_kernel<<<(NN + 1023) / 1024, 1024>>>();
    gemm_mma_kernel<<<gemm_blocks, 1024, gemm_smem>>>(emb, x_idx, W1, b1, attn1, phl);
    scan2_kernel<<<1, 64>>>();
    scan3_kernel<<<(NN + 255) / 256, 256>>>();
    fill_kernel<<<edge_blocks, 256>>>(src, dst, etype);
    relscore_kernel<<<1, 128>>>(rel_emb, Wr1, br1, attn1);

    alpha_kernel<<<edge_blocks, 256>>>();
    aggregate_kernel<<<warp_blocks, 256>>>(emb, x_idx, phl, g1, be1, px2);

    relscore_kernel<<<1, 128>>>(rel_emb, Wr2, br2, attn2);
    gemm_mma_kernel<<<gemm_blocks, 1024, gemm_smem>>>(px2, nullptr, W2, b2, attn2, phl);
    alpha_kernel<<<edge_blocks, 256>>>();
    aggregate_kernel<<<warp_blocks, 256>>>(px2, nullptr, phl, g2, be2, out);
}

// round 8
// speedup vs baseline: 1.6393x; 1.0118x over previous
#include <cuda_runtime.h>
#include <cuda_bf16.h>
#include <cstdint>
#include <math.h>

#define NN 50000
#define EE 640000
#define DD 128
#define RR 100
#define EPS 1e-5f

// ---------------- device scratch ----------------
__device__ float    g_hl   [NN * DD];
__device__ float    g_x2   [NN * DD];
__device__ float    g_si   [NN];
__device__ float    g_sj   [NN];
__device__ float    g_rs   [RR];
__device__ int      g_off  [NN + 1];
__device__ int      g_cur  [NN];
__device__ int      g_scan [NN];
__device__ int      g_bsum [64];
__device__ uint2    g_e2   [EE];     // {src | (etype<<17), dst}, CSR order
__device__ float    g_alpha[EE];     // leaky-relu'd attention logit per edge

// m16n8k16 row.col bf16 MMA, D += A*B
__device__ __forceinline__ void mma_bf16(float* d, const uint32_t* a, uint32_t b0, uint32_t b1) {
    asm volatile(
        "mma.sync.aligned.m16n8k16.row.col.f32.bf16.bf16.f32 "
        "{%0,%1,%2,%3}, {%4,%5,%6,%7}, {%8,%9}, {%0,%1,%2,%3};"
        : "+f"(d[0]), "+f"(d[1]), "+f"(d[2]), "+f"(d[3])
        : "r"(a[0]), "r"(a[1]), "r"(a[2]), "r"(a[3]), "r"(b0), "r"(b1));
}

__device__ __forceinline__ uint32_t pack_bf16(float x0, float x1) {
    __nv_bfloat162 h = __floats2bfloat162_rn(x0, x1);
    return *(uint32_t*)&h;
}
__device__ __forceinline__ float bf16_hi_f(float x) {
    return __bfloat162float(__float2bfloat16(x));
}

// ================= CSR build =================
__global__ void zero_off_kernel() {
    int i = blockIdx.x * blockDim.x + threadIdx.x;
    if (i <= NN) g_off[i] = 0;
}
__global__ void count_kernel(const int* __restrict__ dst) {
    int e = blockIdx.x * blockDim.x + threadIdx.x;
    if (e < EE) atomicAdd(&g_off[dst[e]], 1);
}
__global__ void scan1_kernel() {
    __shared__ int wsum[32];
    int t = threadIdx.x, lane = t & 31, w = t >> 5;
    int i = blockIdx.x * 1024 + t;
    int v = (i < NN) ? g_off[i] : 0;
    int x = v;
    #pragma unroll
    for (int o = 1; o < 32; o <<= 1) {
        int y = __shfl_up_sync(0xffffffffu, x, o);
        if (lane >= o) x += y;
    }
    if (lane == 31) wsum[w] = x;
    __syncthreads();
    if (w == 0) {
        int s = wsum[lane];
        #pragma unroll
        for (int o = 1; o < 32; o <<= 1) {
            int y = __shfl_up_sync(0xffffffffu, s, o);
            if (lane >= o) s += y;
        }
        wsum[lane] = s;
    }
    __syncthreads();
    int incl = x + (w ? wsum[w - 1] : 0);
    if (i < NN) g_scan[i] = incl;
    if (t == 1023) g_bsum[blockIdx.x] = incl;
}
__global__ void scan2_kernel() {
    int t = threadIdx.x;   // 64 threads
    __shared__ int sh[64];
    int v = (t < 49) ? g_bsum[t] : 0;
    sh[t] = v;
    __syncthreads();
    #pragma unroll
    for (int o = 1; o < 64; o <<= 1) {
        int x = (t >= o) ? sh[t - o] : 0;
        __syncthreads();
        sh[t] += x;
        __syncthreads();
    }
    if (t < 49) g_bsum[t] = sh[t] - v;
    if (t == 48) g_off[NN] = sh[48];
}
__global__ void scan3_kernel() {
    int i = blockIdx.x * blockDim.x + threadIdx.x;
    if (i >= NN) return;
    int cnt = g_off[i];
    int excl = g_bsum[i >> 10] + g_scan[i] - cnt;
    g_off[i] = excl;
    g_cur[i] = excl;
}
__global__ void fill_kernel(const int* __restrict__ src,
                            const int* __restrict__ dst,
                            const int* __restrict__ etype) {
    int e = blockIdx.x * blockDim.x + threadIdx.x;
    if (e >= EE) return;
    int d = dst[e];
    int pos = atomicAdd(&g_cur[d], 1);
    g_e2[pos] = make_uint2((unsigned)src[e] | ((unsigned)etype[e] << 17), (unsigned)d);
}

// ====== per-relation score: rs[r] = rel_emb[r]·(Wr^T a_r) + br·a_r ==========
__global__ void relscore_kernel(const float* __restrict__ rel_emb,
                                const float* __restrict__ Wr,
                                const float* __restrict__ br,
                                const float* __restrict__ attn) {
    __shared__ float v[DD];
    __shared__ float red[DD];
    const float* ar = attn + 2 * DD;
    int t = threadIdx.x;  // 128
    float acc = 0.f;
    #pragma unroll 4
    for (int d = 0; d < DD; d++) acc += Wr[d * DD + t] * ar[d];
    v[t] = acc;
    red[t] = br[t] * ar[t];
    __syncthreads();
    for (int s = 64; s > 0; s >>= 1) {
        if (t < s) red[t] += red[t + s];
        __syncthreads();
    }
    float c0 = red[0];
    int warp = t >> 5, lane = t & 31;
    for (int r = warp; r < RR; r += 4) {
        float p = 0.f;
        #pragma unroll
        for (int i = 0; i < 4; i++) p += rel_emb[r * DD + lane + 32 * i] * v[lane + 32 * i];
        #pragma unroll
        for (int o = 16; o; o >>= 1) p += __shfl_xor_sync(0xffffffffu, p, o);
        if (lane == 0) g_rs[r] = p + c0;
    }
}

// ====== tensor-core GEMM (mma.sync bf16 m16n8k16, 3-term split) =============
// 1024 threads, 128 rows/CTA. Warp w: rows (w>>2)*16, cols (w&3)*32.
// A and W pre-packed in MMA-fragment order (uint4 per lane) in smem.
// smem u32 layout: AFhi[8192] AFlo[8192] WFhi[8192] WFlo[8192] sSi[512] sSj[512]
__global__ __launch_bounds__(1024, 1) void gemm_mma_kernel(
    const float* __restrict__ X, const int* __restrict__ idx,
    const float* __restrict__ W, const float* __restrict__ bias,
    const float* __restrict__ attn, float* __restrict__ hl) {
    extern __shared__ uint32_t su[];
    uint32_t* AFhi = su;
    uint32_t* AFlo = su + 8192;
    uint32_t* WFhi = su + 16384;
    uint32_t* WFlo = su + 24576;
    float*    sSi  = (float*)(su + 32768);
    float*    sSj  = sSi + 512;

    int tid = threadIdx.x;
    int blockRow = blockIdx.x * 128;

    // ---- load X (gathered) -> A fragments (hi/lo bf16 pairs) ----
    // fragment u32 index for (row, kp):  kp = k/2
    //   k0=kp>>3, tig=kp&3, khalf=(kp>>2)&1, gid=row&7, rbit=(row>>3)&1, wr=row>>4
    //   off = ((k0*8+wr)*32 + gid*4 + tig)*4 + (rbit + 2*khalf)
    for (int i = tid; i < 128 * 32; i += 1024) {
        int r = i >> 5, c4 = i & 31;           // float4 index; k = c4*4
        int row = blockRow + r;
        float4 v = make_float4(0.f, 0.f, 0.f, 0.f);
        if (row < NN) {
            int g = idx ? idx[row] : row;
            v = ((const float4*)X)[(size_t)g * 32 + c4];
        }
        int gid = r & 7, rbit = (r >> 3) & 1, wr = r >> 4;
        #pragma unroll
        for (int p = 0; p < 2; p++) {
            int kp = c4 * 2 + p;
            float x0 = p ? v.z : v.x;
            float x1 = p ? v.w : v.y;
            float h0 = bf16_hi_f(x0), h1 = bf16_hi_f(x1);
            int k0 = kp >> 3, tig = kp & 3, khalf = (kp >> 2) & 1;
            int off = ((k0 * 8 + wr) * 32 + gid * 4 + tig) * 4 + rbit + 2 * khalf;
            AFhi[off] = pack_bf16(x0, x1);
            AFlo[off] = pack_bf16(x0 - h0, x1 - h1);
        }
    }
    // ---- load W -> B fragments ----
    // for (n=j, kp): nt=n>>3, gd=n&7, np=nt>>1, h=nt&1
    //   off = ((k0*8+np)*32 + gd*4 + tig)*4 + (h*2 + khalf)
    for (int i = tid; i < 128 * 32; i += 1024) {
        int j = i >> 5, c4 = i & 31;
        float4 v = ((const float4*)W)[(size_t)j * 32 + c4];
        int nt = j >> 3, gd = j & 7, np = nt >> 1, hh = nt & 1;
        #pragma unroll
        for (int p = 0; p < 2; p++) {
            int kp = c4 * 2 + p;
            float x0 = p ? v.z : v.x;
            float x1 = p ? v.w : v.y;
            float h0 = bf16_hi_f(x0), h1 = bf16_hi_f(x1);
            int k0 = kp >> 3, tig = kp & 3, khalf = (kp >> 2) & 1;
            int off = ((k0 * 8 + np) * 32 + gd * 4 + tig) * 4 + hh * 2 + khalf;
            WFhi[off] = pack_bf16(x0, x1);
            WFlo[off] = pack_bf16(x0 - h0, x1 - h1);
        }
    }
    __syncthreads();

    int w = tid >> 5, lane = tid & 31;
    int wr = w >> 2, wc = w & 3;
    int gid = lane >> 2, tig = lane & 3;

    float acc[4][4];
    #pragma unroll
    for (int nt = 0; nt < 4; nt++)
        #pragma unroll
        for (int q = 0; q < 4; q++) acc[nt][q] = 0.f;

    const uint4* AH = (const uint4*)AFhi;
    const uint4* AL = (const uint4*)AFlo;
    const uint4* WH = (const uint4*)WFhi;
    const uint4* WL = (const uint4*)WFlo;

    #pragma unroll
    for (int k0 = 0; k0 < 8; k0++) {
        uint4 ahv = AH[(k0 * 8 + wr) * 32 + lane];
        uint4 alv = AL[(k0 * 8 + wr) * 32 + lane];
        uint32_t ah[4] = { ahv.x, ahv.y, ahv.z, ahv.w };
        uint32_t al[4] = { alv.x, alv.y, alv.z, alv.w };
        #pragma unroll
        for (int npl = 0; npl < 2; npl++) {
            int np = wc * 2 + npl;
            uint4 bh = WH[(k0 * 8 + np) * 32 + lane];
            uint4 bl = WL[(k0 * 8 + np) * 32 + lane];
            mma_bf16(acc[npl * 2],     ah, bh.x, bh.y);
            mma_bf16(acc[npl * 2],     al, bh.x, bh.y);
            mma_bf16(acc[npl * 2],     ah, bl.x, bl.y);
            mma_bf16(acc[npl * 2 + 1], ah, bh.z, bh.w);
            mma_bf16(acc[npl * 2 + 1], al, bh.z, bh.w);
            mma_bf16(acc[npl * 2 + 1], ah, bl.z, bl.w);
        }
    }

    // epilogue: bias, store hl, partial attention scores for this col quarter
    int r0l = wr * 16 + gid, r1l = r0l + 8;
    int r0 = blockRow + r0l, r1 = blockRow + r1l;
    float si0 = 0.f, sj0 = 0.f, si1 = 0.f, sj1 = 0.f;
    #pragma unroll
    for (int ntl = 0; ntl < 4; ntl++) {
        int c0 = wc * 32 + ntl * 8 + tig * 2;
        float bb0 = bias[c0], bb1 = bias[c0 + 1];
        float v00 = acc[ntl][0] + bb0, v01 = acc[ntl][1] + bb1;
        float v10 = acc[ntl][2] + bb0, v11 = acc[ntl][3] + bb1;
        float ai0 = attn[c0], ai1 = attn[c0 + 1];
        float aj0 = attn[DD + c0], aj1 = attn[DD + c0 + 1];
        si0 += v00 * ai0 + v01 * ai1;
        sj0 += v00 * aj0 + v01 * aj1;
        si1 += v10 * ai0 + v11 * ai1;
        sj1 += v10 * aj0 + v11 * aj1;
        if (r0 < NN) *(float2*)&hl[(size_t)r0 * DD + c0] = make_float2(v00, v01);
        if (r1 < NN) *(float2*)&hl[(size_t)r1 * DD + c0] = make_float2(v10, v11);
    }
    #pragma unroll
    for (int o = 1; o <= 2; o <<= 1) {
        si0 += __shfl_xor_sync(0xffffffffu, si0, o);
        sj0 += __shfl_xor_sync(0xffffffffu, sj0, o);
        si1 += __shfl_xor_sync(0xffffffffu, si1, o);
        sj1 += __shfl_xor_sync(0xffffffffu, sj1, o);
    }
    if (tig == 0) {
        sSi[r0l * 4 + wc] = si0; sSj[r0l * 4 + wc] = sj0;
        sSi[r1l * 4 + wc] = si1; sSj[r1l * 4 + wc] = sj1;
    }
    __syncthreads();
    if (tid < 128) {
        int row = blockRow + tid;
        if (row < NN) {
            g_si[row] = sSi[tid * 4] + sSi[tid * 4 + 1] + sSi[tid * 4 + 2] + sSi[tid * 4 + 3];
            g_sj[row] = sSj[tid * 4] + sSj[tid * 4 + 1] + sSj[tid * 4 + 2] + sSj[tid * 4 + 3];
        }
    }
}

// ====== edge-parallel attention logit ======
__global__ void alpha_kernel() {
    int e = blockIdx.x * blockDim.x + threadIdx.x;
    if (e >= EE) return;
    uint2 p = g_e2[e];
    int s  = (int)(p.x & 0x1FFFFu);
    int ty = (int)(p.x >> 17);
    int d  = (int)p.y;
    float al = g_si[d] + g_sj[s] + g_rs[ty];
    g_alpha[e] = (al > 0.f) ? al : 0.2f * al;
}

// ====== warp-per-dst two-pass softmax aggregate + residual + LN + ReLU =======
__global__ void aggregate_kernel(const float* __restrict__ xin,
                                 const int* __restrict__ idx,
                                 const float* __restrict__ hl,
                                 const float* __restrict__ gamma,
                                 const float* __restrict__ beta,
                                 float* __restrict__ xout) {
    int w = (blockIdx.x * blockDim.x + threadIdx.x) >> 5;
    int lane = threadIdx.x & 31;
    if (w >= NN) return;

    int beg = g_off[w], end = g_off[w + 1];

    float m = -3.402823466e38f;
    #pragma unroll 4
    for (int e = beg; e < end; e++) m = fmaxf(m, g_alpha[e]);

    float den = 0.f;
    float ax = 0.f, ay = 0.f, az = 0.f, aw = 0.f;
    #pragma unroll 2
    for (int e = beg; e < end; e++) {
        float pe = __expf(g_alpha[e] - m);
        int s = (int)(g_e2[e].x & 0x1FFFFu);
        float4 h = *(const float4*)&hl[(size_t)s * DD + lane * 4];
        ax += pe * h.x;
        ay += pe * h.y;
        az += pe * h.z;
        aw += pe * h.w;
        den += pe;
    }
    float inv = (den > 0.f) ? (1.f / den) : 0.f;

    int xrow = idx ? idx[w] : w;
    float4 xi = *(const float4*)&xin[(size_t)xrow * DD + lane * 4];
    float yx = xi.x + ax * inv;
    float yy = xi.y + ay * inv;
    float yz = xi.z + az * inv;
    float yw = xi.w + aw * inv;

    float sum = yx + yy + yz + yw;
    #pragma unroll
    for (int o = 16; o; o >>= 1) sum += __shfl_xor_sync(0xffffffffu, sum, o);
    float mu = sum * (1.f / 128.f);
    float dx = yx - mu, dy = yy - mu, dz = yz - mu, dw = yw - mu;
    float sq = dx * dx + dy * dy + dz * dz + dw * dw;
    #pragma unroll
    for (int o = 16; o; o >>= 1) sq += __shfl_xor_sync(0xffffffffu, sq, o);
    float var = sq * (1.f / 128.f);
    float rsd = rsqrtf(var + EPS);

    float4 g4 = *(const float4*)&gamma[lane * 4];
    float4 b4 = *(const float4*)&beta[lane * 4];
    float4 o;
    o.x = fmaxf(0.f, dx * rsd * g4.x + b4.x);
    o.y = fmaxf(0.f, dy * rsd * g4.y + b4.y);
    o.z = fmaxf(0.f, dz * rsd * g4.z + b4.z);
    o.w = fmaxf(0.f, dw * rsd * g4.w + b4.w);
    *(float4*)&xout[(size_t)w * DD + lane * 4] = o;
}

// ---------------- launch ----------------
extern "C" void kernel_launch(void* const* d_in, const int* in_sizes, int n_in,
                              void* d_out, int out_size) {
    const int*   x_idx   = (const int*)  d_in[0];
    const int*   eidx    = (const int*)  d_in[1];
    const int*   etype   = (const int*)  d_in[2];
    const float* emb     = (const float*)d_in[3];
    const float* rel_emb = (const float*)d_in[4];
    const float* W1      = (const float*)d_in[5];
    const float* b1      = (const float*)d_in[6];
    const float* Wr1     = (const float*)d_in[7];
    const float* br1     = (const float*)d_in[8];
    const float* attn1   = (const float*)d_in[9];
    const float* g1      = (const float*)d_in[10];
    const float* be1     = (const float*)d_in[11];
    const float* W2      = (const float*)d_in[12];
    const float* b2      = (const float*)d_in[13];
    const float* Wr2     = (const float*)d_in[14];
    const float* br2     = (const float*)d_in[15];
    const float* attn2   = (const float*)d_in[16];
    const float* g2      = (const float*)d_in[17];
    const float* be2     = (const float*)d_in[18];
    float* out = (float*)d_out;

    const int* src = eidx;
    const int* dst = eidx + EE;

    float* phl = nullptr; cudaGetSymbolAddress((void**)&phl, g_hl);
    float* px2 = nullptr; cudaGetSymbolAddress((void**)&px2, g_x2);

    const int gemm_smem = (32768 + 1024) * (int)sizeof(uint32_t);   // 135168
    cudaFuncSetAttribute(gemm_mma_kernel,
                         cudaFuncAttributeMaxDynamicSharedMemorySize, gemm_smem);

    const int gemm_blocks = (NN + 127) / 128;          // 391
    const int warp_blocks = (NN * 32 + 255) / 256;
    const int edge_blocks = (EE + 255) / 256;

    zero_off_kernel<<<(NN + 256) / 256, 256>>>();
    count_kernel<<<edge_blocks, 256>>>(dst);
    scan1_kernel<<<(NN + 1023) / 1024, 1024>>>();
    gemm_mma_kernel<<<gemm_blocks, 1024, gemm_smem>>>(emb, x_idx, W1, b1, attn1, phl);
    scan2_kernel<<<1, 64>>>();
    scan3_kernel<<<(NN + 255) / 256, 256>>>();
    fill_kernel<<<edge_blocks, 256>>>(src, dst, etype);
    relscore_kernel<<<1, 128>>>(rel_emb, Wr1, br1, attn1);

    alpha_kernel<<<edge_blocks, 256>>>();
    aggregate_kernel<<<warp_blocks, 256>>>(emb, x_idx, phl, g1, be1, px2);

    relscore_kernel<<<1, 128>>>(rel_emb, Wr2, br2, attn2);
    gemm_mma_kernel<<<gemm_blocks, 1024, gemm_smem>>>(px2, nullptr, W2, b2, attn2, phl);
    alpha_kernel<<<edge_blocks, 256>>>();
    aggregate_kernel<<<warp_blocks, 256>>>(px2, nullptr, phl, g2, be2, out);
}